// round 11
// baseline (speedup 1.0000x reference)
#include <cuda_runtime.h>
#include <cuda_bf16.h>
#include <cstdint>

// ContrastiveLoss B=8192 D=128 T=0.1, classes c=2*tt+tp in {0..3}
// Round 11: R10 + class-sorted rows. Pure-block pairs with cls_x^cls_j not in
// {1,2} contribute nothing -> skip tile entirely (~half of all symmetric jobs).
// Stride-2 d-windows avoid the contiguous-class imbalance. MMA/epilogue code
// is identical to passing R10.

#define B_SZ 8192
#define RSB  272u                 // smem row stride bytes (256 data + 16 pad)
#define ATILE 17408u              // 64 rows * 272
#define OFF_B   34816u            // + buf*34816 ; hi +0, lo +17408
#define OFF_CLS 104448u           // + buf*64
#define OFF_RED 104576u           // 3072 B scratch
#define OFF_JOBS 107648u          // 67 ints
#define SMEM_BYTES (107648 + 512 + 1024)

// ---------------------------------------------------------------- globals
__device__ __align__(256) __nv_bfloat16 g_hi[B_SZ * 128];
__device__ __align__(256) __nv_bfloat16 g_lo[B_SZ * 128];
__device__ int           g_cls_orig[B_SZ];
__device__ int           g_newpos[B_SZ];
__device__ int           g_cls[B_SZ];        // sorted
__device__ __align__(256) unsigned char g_clsb[B_SZ];  // sorted
__device__ unsigned char g_blockcls[128];    // pure class or 255 if mixed
__device__ int           g_cnt4[4];
__device__ float4        g_rpart[2][B_SZ];
__device__ float4        g_cpart[64][B_SZ];
__device__ float         g_rowval[B_SZ];
__device__ int           g_is64;

// ---------------------------------------------------------------- helpers
__device__ __forceinline__ uint32_t smem_u32(const void* p) {
    uint32_t a;
    asm("{ .reg .u64 t; cvta.to.shared.u64 t, %1; cvt.u32.u64 %0, t; }" : "=r"(a) : "l"(p));
    return a;
}
__device__ __forceinline__ void cp16(uint32_t dst, const void* src) {
    asm volatile("cp.async.cg.shared.global [%0], [%1], 16;" :: "r"(dst), "l"(src) : "memory");
}
__device__ __forceinline__ void cp_commit() {
    asm volatile("cp.async.commit_group;" ::: "memory");
}
__device__ __forceinline__ void cp_wait0() {
    asm volatile("cp.async.wait_group 0;" ::: "memory");
}
__device__ __forceinline__ void cp_wait1() {
    asm volatile("cp.async.wait_group 1;" ::: "memory");
}
__device__ __forceinline__ void ldsm4(uint32_t* r, uint32_t addr) {
    asm volatile("ldmatrix.sync.aligned.m8n8.x4.shared.b16 {%0,%1,%2,%3}, [%4];"
                 : "=r"(r[0]), "=r"(r[1]), "=r"(r[2]), "=r"(r[3]) : "r"(addr));
}
__device__ __forceinline__ void mma_bf16(float* c, const uint32_t* a, uint32_t b0, uint32_t b1) {
    asm volatile(
        "mma.sync.aligned.m16n8k16.row.col.f32.bf16.bf16.f32 "
        "{%0,%1,%2,%3}, {%4,%5,%6,%7}, {%8,%9}, {%0,%1,%2,%3};"
        : "+f"(c[0]), "+f"(c[1]), "+f"(c[2]), "+f"(c[3])
        : "r"(a[0]), "r"(a[1]), "r"(a[2]), "r"(a[3]), "r"(b0), "r"(b1));
}
__device__ __forceinline__ float ex2f(float v) {
    float e;
    asm("ex2.approx.ftz.f32 %0, %1;" : "=f"(e) : "f"(v));
    return e;
}

// async load one hi+lo 64-row tile (256 B/row) into padded smem rows
__device__ __forceinline__ void load_tile64(uint32_t sdst_h, int rowbase, int tid) {
#pragma unroll
    for (int i = 0; i < 4; ++i) {
        int idx = tid + i * 256;             // 0..1023
        int r = idx >> 4, c = idx & 15;
        uint32_t dst = sdst_h + (uint32_t)r * RSB + (uint32_t)c * 16u;
        cp16(dst, g_hi + (size_t)(rowbase + r) * 128 + c * 8);
        cp16(dst + ATILE, g_lo + (size_t)(rowbase + r) * 128 + c * 8);
    }
}

// ---------------------------------------------------------------- zero partials
__global__ void zero_kernel() {
    size_t n = (size_t)64 * B_SZ + 2 * B_SZ;
    float4* base = &g_cpart[0][0];
    float4* rp = &g_rpart[0][0];
    size_t idx = (size_t)blockIdx.x * blockDim.x + threadIdx.x;
    size_t stride = (size_t)gridDim.x * blockDim.x;
    for (size_t i = idx; i < n; i += stride) {
        if (i < (size_t)64 * B_SZ) base[i] = make_float4(0.f, 0.f, 0.f, 0.f);
        else rp[i - (size_t)64 * B_SZ] = make_float4(0.f, 0.f, 0.f, 0.f);
    }
}

// ---------------------------------------------------------------- detect
__global__ void detect_kernel(const long long* __restrict__ dix64) {
    __shared__ int bad;
    if (threadIdx.x == 0) bad = 0;
    __syncthreads();
    int local = 0;
    for (int i = threadIdx.x; i < 4096; i += blockDim.x) {
        long long v = dix64[i];
        if (v < 0 || v >= 100000) local = 1;
    }
    if (local) atomicOr(&bad, 1);
    __syncthreads();
    if (threadIdx.x == 0) g_is64 = (bad == 0) ? 1 : 0;
}

// ---------------------------------------------------------------- classes (orig order)
__global__ void cls_kernel(const void* __restrict__ data_ix,
                           const void* __restrict__ tt,
                           const void* __restrict__ tp) {
    int i = blockIdx.x * 256 + threadIdx.x;
    long long ix;
    int t, p;
    if (g_is64) {
        ix = ((const long long*)data_ix)[i];
        t = (int)((const long long*)tt)[ix];
        p = (int)((const long long*)tp)[ix];
    } else {
        ix = (long long)((const int*)data_ix)[i];
        t = ((const int*)tt)[i < 0 ? 0 : (int)ix];
        p = ((const int*)tp)[(int)ix];
    }
    g_cls_orig[i] = t * 2 + p;
}

// ---------------------------------------------------------------- deterministic rank/scatter
// single CTA, 256 threads, 32 rows each: counting sort by class (stable).
__global__ void rank_kernel() {
    __shared__ int cnt[256][4];
    __shared__ int base[4];
    int t = threadIdx.x;
    int lc[4] = {0, 0, 0, 0};
#pragma unroll 4
    for (int r = 0; r < 32; ++r) lc[g_cls_orig[t * 32 + r]]++;
#pragma unroll
    for (int c = 0; c < 4; ++c) cnt[t][c] = lc[c];
    __syncthreads();
    if (t == 0) {
        int tot[4] = {0, 0, 0, 0};
        for (int u = 0; u < 256; ++u)
            for (int c = 0; c < 4; ++c) tot[c] += cnt[u][c];
        base[0] = 0; base[1] = tot[0];
        base[2] = tot[0] + tot[1]; base[3] = tot[0] + tot[1] + tot[2];
        int run[4] = {base[0], base[1], base[2], base[3]};
        for (int u = 0; u < 256; ++u)
            for (int c = 0; c < 4; ++c) { int tmp = cnt[u][c]; cnt[u][c] = run[c]; run[c] += tmp; }
        for (int c = 0; c < 4; ++c) g_cnt4[c] = tot[c];
    }
    __syncthreads();
    int off[4] = {cnt[t][0], cnt[t][1], cnt[t][2], cnt[t][3]};
    for (int r = 0; r < 32; ++r) {
        int i = t * 32 + r;
        int c = g_cls_orig[i];
        int np = off[c]++;
        g_newpos[i] = np;
        g_cls[np] = c;
        g_clsb[np] = (unsigned char)c;
    }
    __syncthreads();   // same-CTA global writes visible after barrier
    if (t < 128) {
        int c0 = g_cls[t * 64], c1 = g_cls[t * 64 + 63];   // sorted -> pure iff ends match
        g_blockcls[t] = (c0 == c1) ? (unsigned char)c0 : (unsigned char)255;
    }
}

// ---------------------------------------------------------------- prep (normalize+split, scatter)
__global__ void prep_kernel(const float* __restrict__ F) {
    int warp = (blockIdx.x * blockDim.x + threadIdx.x) >> 5;
    int lane = threadIdx.x & 31;
    const float* row = F + (size_t)warp * 128;
    float v0 = row[lane], v1 = row[lane + 32], v2 = row[lane + 64], v3 = row[lane + 96];
    float ss = v0 * v0 + v1 * v1 + v2 * v2 + v3 * v3;
#pragma unroll
    for (int o = 16; o; o >>= 1) ss += __shfl_xor_sync(0xffffffffu, ss, o);
    float scale = sqrtf(14.4269504088896f) / sqrtf(ss);   // sqrt(log2e / T)
    int np = g_newpos[warp];
    float g[4] = {v0 * scale, v1 * scale, v2 * scale, v3 * scale};
#pragma unroll
    for (int qq = 0; qq < 4; ++qq) {
        __nv_bfloat16 h = __float2bfloat16(g[qq]);
        __nv_bfloat16 lo = __float2bfloat16(g[qq] - __bfloat162float(h));
        g_hi[(size_t)np * 128 + lane + qq * 32] = h;
        g_lo[(size_t)np * 128 + lane + qq * 32] = lo;
    }
}

// ---------------------------------------------------------------- main kernel
// grid (128, 2), 256 thr = 8 warps (2m x 4n), warp tile 32x16.
// CTA (x,q): candidates d = q + 2t (t<32), + d=64 for q==0 && x<64.
// Skip job if both blocks pure and xor(cls) not in {1,2}.
__global__ void __launch_bounds__(256, 2) main_kernel() {
    extern __shared__ char smraw[];
    char* smp = (char*)(((uintptr_t)smraw + 1023) & ~(uintptr_t)1023);
    const uint32_t sb = smem_u32(smp);
    float* red = (float*)(smp + OFF_RED);
    int* jobs = (int*)(smp + OFF_JOBS);      // [2*33] d,tj pairs + [66] count

    const int tid = threadIdx.x;
    const int l = tid & 31, wid = tid >> 5;
    const int warp_m = wid >> 2, warp_n = wid & 3;
    const int x = blockIdx.x, q = blockIdx.y;

    // A tile (persistent)
    load_tile64(sb + 0u, x * 64, tid);
    cp_commit();

    // build filtered job list
    if (tid == 0) {
        int n = 0;
        int bcx = g_blockcls[x];
        int ncand = 32 + ((q == 0 && x < 64) ? 1 : 0);
        for (int t = 0; t < ncand; ++t) {
            int d = (t < 32) ? (q + 2 * t) : 64;
            int tj = (x + d) & 127;
            int bcj = g_blockcls[tj];
            int xr = bcx ^ bcj;
            bool skip = (bcx < 4 && bcj < 4) && (xr != 1) && (xr != 2);
            if (!skip) { jobs[2 * n] = d; jobs[2 * n + 1] = tj; ++n; }
        }
        jobs[66] = n;
    }
    __syncthreads();
    const int njobs = jobs[66];

    if (njobs > 0) {
        int tj0 = jobs[1];
        load_tile64(sb + OFF_B, tj0 * 64, tid);
        if (tid < 4) cp16(sb + OFF_CLS + tid * 16u, g_clsb + tj0 * 64 + tid * 16);
        cp_commit();
    }

    const uint32_t laneA = (uint32_t)((warp_m * 32 + (l & 15)) * (int)RSB + ((l >> 4) * 16));
    const uint32_t pAh = sb + laneA;
    const uint32_t pAl = sb + ATILE + laneA;
    const uint32_t laneB = (uint32_t)((warp_n * 16 + (l & 15)) * (int)RSB + ((l >> 4) * 16));

    int pc[4], ncl[4];
#pragma unroll
    for (int ri = 0; ri < 4; ++ri) {
        int row = warp_m * 32 + (ri >> 1) * 16 + (ri & 1) * 8 + (l >> 2);
        int cr = g_cls[x * 64 + row];
        pc[ri] = cr ^ 1;
        ncl[ri] = cr ^ 2;
    }

    float epos[4] = {0.f, 0.f, 0.f, 0.f};
    float eneg[4] = {0.f, 0.f, 0.f, 0.f};
    float lsum[4] = {0.f, 0.f, 0.f, 0.f};

    for (int t = 0; t < njobs; ++t) {
        const int buf = t & 1;
        const int d = jobs[2 * t];
        const int tj = jobs[2 * t + 1];

        if (t + 1 < njobs) {
            const int tjn = jobs[2 * (t + 1) + 1];
            load_tile64(sb + OFF_B + (uint32_t)(buf ^ 1) * 34816u, tjn * 64, tid);
            if (tid < 4)
                cp16(sb + OFF_CLS + (uint32_t)(buf ^ 1) * 64u + tid * 16u,
                     g_clsb + tjn * 64 + tid * 16);
            cp_commit();
            cp_wait1();
        } else {
            cp_wait0();
        }
        __syncthreads();

        // ---------------- MMA: 64x64 tile, K=128, 3 splits (identical to R10)
        const uint32_t pBh = sb + OFF_B + (uint32_t)buf * 34816u + laneB;
        const uint32_t pBl = pBh + ATILE;

        float acc[2][2][4];
#pragma unroll
        for (int mf = 0; mf < 2; ++mf)
#pragma unroll
            for (int nf = 0; nf < 2; ++nf)
#pragma unroll
                for (int c4 = 0; c4 < 4; ++c4) acc[mf][nf][c4] = 0.f;

#pragma unroll 1
        for (int ks = 0; ks < 8; ++ks) {
            const uint32_t ko = (uint32_t)ks * 32u;
            uint32_t aH[2][4], aL[2][4], bh[4], bl[4];
            ldsm4(aH[0], pAh + ko);
            ldsm4(aH[1], pAh + 16u * RSB + ko);
            ldsm4(aL[0], pAl + ko);
            ldsm4(aL[1], pAl + 16u * RSB + ko);
            ldsm4(bh, pBh + ko);
            ldsm4(bl, pBl + ko);
#pragma unroll
            for (int nf = 0; nf < 2; ++nf)
#pragma unroll
                for (int mf = 0; mf < 2; ++mf)
                    mma_bf16(acc[mf][nf], aH[mf], bh[nf], bh[nf + 2]);
#pragma unroll
            for (int nf = 0; nf < 2; ++nf)
#pragma unroll
                for (int mf = 0; mf < 2; ++mf)
                    mma_bf16(acc[mf][nf], aH[mf], bl[nf], bl[nf + 2]);
#pragma unroll
            for (int nf = 0; nf < 2; ++nf)
#pragma unroll
                for (int mf = 0; mf < 2; ++mf)
                    mma_bf16(acc[mf][nf], aL[mf], bh[nf], bh[nf + 2]);
        }

        // ---------------- epilogue (identical to R10)
        const float dc = (d != 0) ? 1.0f : 0.0f;
        const uint32_t clsb_s = sb + OFF_CLS + (uint32_t)buf * 64u +
                                (uint32_t)(warp_n * 16 + 2 * (l & 3));
#pragma unroll
        for (int nf = 0; nf < 2; ++nf) {
            unsigned short cw;
            asm volatile("ld.shared.u16 %0, [%1];" : "=h"(cw) : "r"(clsb_s + (uint32_t)nf * 8u));
            const int cj0 = cw & 0xff, cj1 = cw >> 8;
            float cE0 = 0.f, cE1 = 0.f, cN0 = 0.f, cN1 = 0.f, cL0 = 0.f, cL1 = 0.f;
#pragma unroll
            for (int ri = 0; ri < 4; ++ri) {
                float v0 = acc[ri >> 1][nf][(ri & 1) * 2 + 0];
                float v1 = acc[ri >> 1][nf][(ri & 1) * 2 + 1];
                float e0 = ex2f(v0), e1 = ex2f(v1);
                if (cj0 == pc[ri]) { epos[ri] += e0; lsum[ri] += v0;
                                     cE0 += dc * e0; cL0 += dc * v0; }
                else if (cj0 == ncl[ri]) { eneg[ri] += e0; cN0 += dc * e0; }
                if (cj1 == pc[ri]) { epos[ri] += e1; lsum[ri] += v1;
                                     cE1 += dc * e1; cL1 += dc * v1; }
                else if (cj1 == ncl[ri]) { eneg[ri] += e1; cN1 += dc * e1; }
            }
#pragma unroll
            for (int s = 4; s <= 16; s <<= 1) {
                cE0 += __shfl_xor_sync(0xffffffffu, cE0, s);
                cE1 += __shfl_xor_sync(0xffffffffu, cE1, s);
                cN0 += __shfl_xor_sync(0xffffffffu, cN0, s);
                cN1 += __shfl_xor_sync(0xffffffffu, cN1, s);
                cL0 += __shfl_xor_sync(0xffffffffu, cL0, s);
                cL1 += __shfl_xor_sync(0xffffffffu, cL1, s);
            }
            if ((l >> 2) == 0) {
                int col = warp_n * 16 + nf * 8 + 2 * l;
                int base = (warp_m * 64 + col) * 3;
                red[base + 0] = cE0; red[base + 1] = cN0; red[base + 2] = cL0;
                red[base + 3] = cE1; red[base + 4] = cN1; red[base + 5] = cL1;
            }
        }
        __syncthreads();
        if (d != 0 && tid < 64) {
            float E = red[tid * 3 + 0] + red[(64 + tid) * 3 + 0];
            float N = red[tid * 3 + 1] + red[(64 + tid) * 3 + 1];
            float L = red[tid * 3 + 2] + red[(64 + tid) * 3 + 2];
            g_cpart[d - 1][tj * 64 + tid] = make_float4(E, N, L, 0.f);
        }
        __syncthreads();
    }
    if (njobs == 0) cp_wait0();   // drain A-tile cp.async before exit path

    // ---------------- row flush
#pragma unroll
    for (int ri = 0; ri < 4; ++ri) {
        epos[ri] += __shfl_xor_sync(0xffffffffu, epos[ri], 1);
        epos[ri] += __shfl_xor_sync(0xffffffffu, epos[ri], 2);
        eneg[ri] += __shfl_xor_sync(0xffffffffu, eneg[ri], 1);
        eneg[ri] += __shfl_xor_sync(0xffffffffu, eneg[ri], 2);
        lsum[ri] += __shfl_xor_sync(0xffffffffu, lsum[ri], 1);
        lsum[ri] += __shfl_xor_sync(0xffffffffu, lsum[ri], 2);
    }
    if ((l & 3) == 0) {
#pragma unroll
        for (int ri = 0; ri < 4; ++ri) {
            int row = warp_m * 32 + (ri >> 1) * 16 + (ri & 1) * 8 + (l >> 2);
            red[(row * 4 + warp_n) * 3 + 0] = epos[ri];
            red[(row * 4 + warp_n) * 3 + 1] = eneg[ri];
            red[(row * 4 + warp_n) * 3 + 2] = lsum[ri];
        }
    }
    __syncthreads();
    if (tid < 64) {
        float Ep = 0.f, En = 0.f, Ls = 0.f;
#pragma unroll
        for (int wn = 0; wn < 4; ++wn) {
            Ep += red[(tid * 4 + wn) * 3 + 0];
            En += red[(tid * 4 + wn) * 3 + 1];
            Ls += red[(tid * 4 + wn) * 3 + 2];
        }
        g_rpart[q][x * 64 + tid] = make_float4(Ep, En, Ls, 0.f);
    }
}

// ---------------------------------------------------------------- per-row values
__global__ void rowval_kernel() {
    int tid = threadIdx.x;
    int i = blockIdx.x * 128 + (tid >> 1);
    int p = tid & 1;
    float Ep = 0.f, En = 0.f, Ls = 0.f;
#pragma unroll
    for (int s = 0; s < 33; ++s) {
        int sl = p * 33 + s;
        float4 v = (sl < 2) ? g_rpart[sl][i] : g_cpart[sl - 2][i];
        Ep += v.x; En += v.y; Ls += v.z;
    }
    Ep += __shfl_xor_sync(0xffffffffu, Ep, 1);
    En += __shfl_xor_sync(0xffffffffu, En, 1);
    Ls += __shfl_xor_sync(0xffffffffu, Ls, 1);
    if (p == 0) {
        int ci = g_cls[i];
        int pcnt = g_cnt4[ci ^ 1];
        int ncnt = g_cnt4[ci ^ 2];
        float val = 0.f;
        if (pcnt > 0 && ncnt > 0)
            val = (Ls * 0.6931471805599453f - (float)pcnt * logf(Ep + En)) / (float)pcnt;
        g_rowval[i] = val;
    }
}

// ---------------------------------------------------------------- final sum
__global__ void sum_kernel(float* __restrict__ out) {
    __shared__ float s[256];
    float acc = 0.f;
    for (int i = threadIdx.x; i < B_SZ; i += 256) acc += g_rowval[i];
    s[threadIdx.x] = acc;
    __syncthreads();
    for (int o = 128; o; o >>= 1) {
        if (threadIdx.x < o) s[threadIdx.x] += s[threadIdx.x + o];
        __syncthreads();
    }
    if (threadIdx.x == 0) out[0] = -s[0] / (float)B_SZ;
}

// ---------------------------------------------------------------- launch
extern "C" void kernel_launch(void* const* d_in, const int* in_sizes, int n_in,
                              void* d_out, int out_size) {
    const float* F = (const float*)d_in[0];
    const void* dix = d_in[1];
    const void* tt  = d_in[2];
    const void* tp  = d_in[3];
    float* out = (float*)d_out;

    zero_kernel<<<512, 256>>>();
    detect_kernel<<<1, 256>>>((const long long*)dix);
    cls_kernel<<<32, 256>>>(dix, tt, tp);
    rank_kernel<<<1, 256>>>();
    prep_kernel<<<(B_SZ * 32) / 256, 256>>>(F);

    cudaFuncSetAttribute(main_kernel, cudaFuncAttributeMaxDynamicSharedMemorySize, SMEM_BYTES);
    main_kernel<<<dim3(128, 2), 256, SMEM_BYTES>>>();

    rowval_kernel<<<64, 256>>>();
    sum_kernel<<<1, 256>>>(out);
}

// round 12
// speedup vs baseline: 1.3840x; 1.3840x over previous
#include <cuda_runtime.h>
#include <cuda_bf16.h>
#include <cstdint>

// ContrastiveLoss B=8192 D=128 T=0.1, classes c=2*tt+tp in {0..3}
// Round 12: class-sorted rows + GLOBAL flattened job list (perfect balance),
// parallel rank kernel. Pure-pair blocks with xor not in {1,2} skipped.
// MMA/epilogue bodies identical to passing R10/R11.

#define B_SZ 8192
#define RSB  272u
#define ATILE 17408u              // 64 rows * 272
#define OFF_B   34816u            // + buf*34816 ; hi +0, lo +17408
#define OFF_CLS 104448u           // + buf*64
#define OFF_RED 104576u           // 3072 B scratch
#define SMEM_BYTES (104576 + 3072 + 1024)
#define NCTA 256

// ---------------------------------------------------------------- globals
__device__ __align__(256) __nv_bfloat16 g_hi[B_SZ * 128];
__device__ __align__(256) __nv_bfloat16 g_lo[B_SZ * 128];
__device__ int           g_cls_orig[B_SZ];
__device__ int           g_newpos[B_SZ];
__device__ int           g_cls[B_SZ];
__device__ __align__(256) unsigned char g_clsb[B_SZ];
__device__ unsigned char g_blockcls[128];
__device__ int           g_cnt4[4];
__device__ int           g_joblist[8448];    // (x<<8)|d, grouped by x
__device__ int           g_njobs;
__device__ float4        g_rpart[8][B_SZ];   // row partials per CTA slot
__device__ float4        g_cpart[64][B_SZ];  // col partials per (d-1)
__device__ float         g_rowval[B_SZ];
__device__ int           g_is64;

// ---------------------------------------------------------------- helpers
__device__ __forceinline__ uint32_t smem_u32(const void* p) {
    uint32_t a;
    asm("{ .reg .u64 t; cvta.to.shared.u64 t, %1; cvt.u32.u64 %0, t; }" : "=r"(a) : "l"(p));
    return a;
}
__device__ __forceinline__ void cp16(uint32_t dst, const void* src) {
    asm volatile("cp.async.cg.shared.global [%0], [%1], 16;" :: "r"(dst), "l"(src) : "memory");
}
__device__ __forceinline__ void cp_commit() {
    asm volatile("cp.async.commit_group;" ::: "memory");
}
__device__ __forceinline__ void cp_wait0() {
    asm volatile("cp.async.wait_group 0;" ::: "memory");
}
__device__ __forceinline__ void cp_wait1() {
    asm volatile("cp.async.wait_group 1;" ::: "memory");
}
__device__ __forceinline__ void ldsm4(uint32_t* r, uint32_t addr) {
    asm volatile("ldmatrix.sync.aligned.m8n8.x4.shared.b16 {%0,%1,%2,%3}, [%4];"
                 : "=r"(r[0]), "=r"(r[1]), "=r"(r[2]), "=r"(r[3]) : "r"(addr));
}
__device__ __forceinline__ void mma_bf16(float* c, const uint32_t* a, uint32_t b0, uint32_t b1) {
    asm volatile(
        "mma.sync.aligned.m16n8k16.row.col.f32.bf16.bf16.f32 "
        "{%0,%1,%2,%3}, {%4,%5,%6,%7}, {%8,%9}, {%0,%1,%2,%3};"
        : "+f"(c[0]), "+f"(c[1]), "+f"(c[2]), "+f"(c[3])
        : "r"(a[0]), "r"(a[1]), "r"(a[2]), "r"(a[3]), "r"(b0), "r"(b1));
}
__device__ __forceinline__ float ex2f(float v) {
    float e;
    asm("ex2.approx.ftz.f32 %0, %1;" : "=f"(e) : "f"(v));
    return e;
}

__device__ __forceinline__ void load_tile64(uint32_t sdst_h, int rowbase, int tid) {
#pragma unroll
    for (int i = 0; i < 4; ++i) {
        int idx = tid + i * 256;
        int r = idx >> 4, c = idx & 15;
        uint32_t dst = sdst_h + (uint32_t)r * RSB + (uint32_t)c * 16u;
        cp16(dst, g_hi + (size_t)(rowbase + r) * 128 + c * 8);
        cp16(dst + ATILE, g_lo + (size_t)(rowbase + r) * 128 + c * 8);
    }
}

// ---------------------------------------------------------------- zero partials
__global__ void zero_kernel() {
    size_t n = (size_t)(64 + 8) * B_SZ;
    float4* cp = &g_cpart[0][0];
    float4* rp = &g_rpart[0][0];
    size_t idx = (size_t)blockIdx.x * blockDim.x + threadIdx.x;
    size_t stride = (size_t)gridDim.x * blockDim.x;
    for (size_t i = idx; i < n; i += stride) {
        if (i < (size_t)64 * B_SZ) cp[i] = make_float4(0.f, 0.f, 0.f, 0.f);
        else rp[i - (size_t)64 * B_SZ] = make_float4(0.f, 0.f, 0.f, 0.f);
    }
}

// ---------------------------------------------------------------- detect
__global__ void detect_kernel(const long long* __restrict__ dix64) {
    __shared__ int bad;
    if (threadIdx.x == 0) bad = 0;
    __syncthreads();
    int local = 0;
    for (int i = threadIdx.x; i < 4096; i += blockDim.x) {
        long long v = dix64[i];
        if (v < 0 || v >= 100000) local = 1;
    }
    if (local) atomicOr(&bad, 1);
    __syncthreads();
    if (threadIdx.x == 0) g_is64 = (bad == 0) ? 1 : 0;
}

// ---------------------------------------------------------------- classes (orig order)
__global__ void cls_kernel(const void* __restrict__ data_ix,
                           const void* __restrict__ tt,
                           const void* __restrict__ tp) {
    int i = blockIdx.x * 256 + threadIdx.x;
    int t, p;
    if (g_is64) {
        long long ix = ((const long long*)data_ix)[i];
        t = (int)((const long long*)tt)[ix];
        p = (int)((const long long*)tp)[ix];
    } else {
        int ix = ((const int*)data_ix)[i];
        t = ((const int*)tt)[ix];
        p = ((const int*)tp)[ix];
    }
    g_cls_orig[i] = t * 2 + p;
}

// ---------------------------------------------------------------- rank (parallel scans)
__global__ void rank_kernel() {
    __shared__ int wsum[4][8];
    __shared__ int tot_sh[4];
    int t = threadIdx.x, lane = t & 31, w = t >> 5;
    int lc[4] = {0, 0, 0, 0};
    for (int r = 0; r < 32; ++r) lc[g_cls_orig[t * 32 + r]]++;
    int ex[4];
#pragma unroll
    for (int c = 0; c < 4; ++c) {
        int v = lc[c];
#pragma unroll
        for (int o = 1; o < 32; o <<= 1) {
            int u = __shfl_up_sync(0xffffffffu, v, o);
            if (lane >= o) v += u;
        }
        if (lane == 31) wsum[c][w] = v;
        ex[c] = v - lc[c];
    }
    __syncthreads();
    if (t < 4) {
        int run = 0;
        for (int u = 0; u < 8; ++u) { int tmp = wsum[t][u]; wsum[t][u] = run; run += tmp; }
        tot_sh[t] = run;
        g_cnt4[t] = run;
    }
    __syncthreads();
    int base[4];
    base[0] = 0;
    base[1] = tot_sh[0];
    base[2] = base[1] + tot_sh[1];
    base[3] = base[2] + tot_sh[2];
    int off[4];
#pragma unroll
    for (int c = 0; c < 4; ++c) off[c] = base[c] + wsum[c][w] + ex[c];
    for (int r = 0; r < 32; ++r) {
        int i = t * 32 + r;
        int c = g_cls_orig[i];
        int np = off[c]++;
        g_newpos[i] = np;
        g_cls[np] = c;
        g_clsb[np] = (unsigned char)c;
    }
    __syncthreads();
    if (t < 128) {
        int c0 = g_cls[t * 64], c1 = g_cls[t * 64 + 63];
        g_blockcls[t] = (c0 == c1) ? (unsigned char)c0 : (unsigned char)255;
    }
}

// ---------------------------------------------------------------- job list (128 threads)
__global__ void joblist_kernel() {
    __shared__ int woff[4];
    int x = threadIdx.x;            // 0..127
    int lane = x & 31, w = x >> 5;
    int bcx = g_blockcls[x];
    int ncand = 64 + (x < 64 ? 1 : 0);
    int n = 0;
#pragma unroll 1
    for (int d = 0; d <= 64; ++d) {
        if (d == 64 && x >= 64) break;
        int tj = (x + d) & 127;
        int bcj = g_blockcls[tj];
        int xr = bcx ^ bcj;
        bool skip = (bcx < 4 && bcj < 4) && (xr != 1) && (xr != 2);
        if (!skip) ++n;
    }
    (void)ncand;
    int v = n;
#pragma unroll
    for (int o = 1; o < 32; o <<= 1) {
        int u = __shfl_up_sync(0xffffffffu, v, o);
        if (lane >= o) v += u;
    }
    if (lane == 31) woff[w] = v;
    int ex = v - n;
    __syncthreads();
    if (x == 0) {
        int run = 0;
        for (int u = 0; u < 4; ++u) { int tmp = woff[u]; woff[u] = run; run += tmp; }
        g_njobs = run;
    }
    __syncthreads();
    int pos = woff[w] + ex;
#pragma unroll 1
    for (int d = 0; d <= 64; ++d) {
        if (d == 64 && x >= 64) break;
        int tj = (x + d) & 127;
        int bcj = g_blockcls[tj];
        int xr = bcx ^ bcj;
        bool skip = (bcx < 4 && bcj < 4) && (xr != 1) && (xr != 2);
        if (!skip) g_joblist[pos++] = (x << 8) | d;
    }
}

// ---------------------------------------------------------------- prep (normalize+split, scatter)
__global__ void prep_kernel(const float* __restrict__ F) {
    int warp = (blockIdx.x * blockDim.x + threadIdx.x) >> 5;
    int lane = threadIdx.x & 31;
    const float* row = F + (size_t)warp * 128;
    float v0 = row[lane], v1 = row[lane + 32], v2 = row[lane + 64], v3 = row[lane + 96];
    float ss = v0 * v0 + v1 * v1 + v2 * v2 + v3 * v3;
#pragma unroll
    for (int o = 16; o; o >>= 1) ss += __shfl_xor_sync(0xffffffffu, ss, o);
    float scale = sqrtf(14.4269504088896f) / sqrtf(ss);
    int np = g_newpos[warp];
    float g[4] = {v0 * scale, v1 * scale, v2 * scale, v3 * scale};
#pragma unroll
    for (int qq = 0; qq < 4; ++qq) {
        __nv_bfloat16 h = __float2bfloat16(g[qq]);
        __nv_bfloat16 lo = __float2bfloat16(g[qq] - __bfloat162float(h));
        g_hi[(size_t)np * 128 + lane + qq * 32] = h;
        g_lo[(size_t)np * 128 + lane + qq * 32] = lo;
    }
}

// ---------------------------------------------------------------- main kernel
// 256 CTAs x 256 thr. CTA k runs jobs [k*M/256, (k+1)*M/256) of the flattened
// list (grouped by x). Prefetch only within an x-run -> zero outstanding
// cp.async groups at every x boundary (A reload is race-free).
__global__ void __launch_bounds__(256, 2) main_kernel() {
    extern __shared__ char smraw[];
    char* smp = (char*)(((uintptr_t)smraw + 1023) & ~(uintptr_t)1023);
    const uint32_t sb = smem_u32(smp);
    float* red = (float*)(smp + OFF_RED);

    const int tid = threadIdx.x;
    const int l = tid & 31, wid = tid >> 5;
    const int warp_m = wid >> 2, warp_n = wid & 3;
    const int cta = blockIdx.x;
    const int slot = cta & 7;

    const int M = g_njobs;
    const int jstart = (int)(((long long)cta * M) / NCTA);
    const int jend   = (int)(((long long)(cta + 1) * M) / NCTA);

    const uint32_t laneA = (uint32_t)((warp_m * 32 + (l & 15)) * (int)RSB + ((l >> 4) * 16));
    const uint32_t pAh = sb + laneA;
    const uint32_t pAl = sb + ATILE + laneA;
    const uint32_t laneB = (uint32_t)((warp_n * 16 + (l & 15)) * (int)RSB + ((l >> 4) * 16));

    float epos[4] = {0.f, 0.f, 0.f, 0.f};
    float eneg[4] = {0.f, 0.f, 0.f, 0.f};
    float lsum[4] = {0.f, 0.f, 0.f, 0.f};
    int pc[4], ncl[4];
    int curx = -1, buf = 0;

    auto flush_rows = [&](int fx) {
#pragma unroll
        for (int ri = 0; ri < 4; ++ri) {
            epos[ri] += __shfl_xor_sync(0xffffffffu, epos[ri], 1);
            epos[ri] += __shfl_xor_sync(0xffffffffu, epos[ri], 2);
            eneg[ri] += __shfl_xor_sync(0xffffffffu, eneg[ri], 1);
            eneg[ri] += __shfl_xor_sync(0xffffffffu, eneg[ri], 2);
            lsum[ri] += __shfl_xor_sync(0xffffffffu, lsum[ri], 1);
            lsum[ri] += __shfl_xor_sync(0xffffffffu, lsum[ri], 2);
        }
        if ((l & 3) == 0) {
#pragma unroll
            for (int ri = 0; ri < 4; ++ri) {
                int row = warp_m * 32 + (ri >> 1) * 16 + (ri & 1) * 8 + (l >> 2);
                red[(row * 4 + warp_n) * 3 + 0] = epos[ri];
                red[(row * 4 + warp_n) * 3 + 1] = eneg[ri];
                red[(row * 4 + warp_n) * 3 + 2] = lsum[ri];
            }
        }
        __syncthreads();
        if (tid < 64) {
            float Ep = 0.f, En = 0.f, Ls = 0.f;
#pragma unroll
            for (int wn = 0; wn < 4; ++wn) {
                Ep += red[(tid * 4 + wn) * 3 + 0];
                En += red[(tid * 4 + wn) * 3 + 1];
                Ls += red[(tid * 4 + wn) * 3 + 2];
            }
            g_rpart[slot][fx * 64 + tid] = make_float4(Ep, En, Ls, 0.f);
        }
        __syncthreads();
#pragma unroll
        for (int ri = 0; ri < 4; ++ri) { epos[ri] = 0.f; eneg[ri] = 0.f; lsum[ri] = 0.f; }
    };

    for (int j = jstart; j < jend; ++j) {
        const int job = g_joblist[j];
        const int x = job >> 8, d = job & 255;
        const int tj = (x + d) & 127;

        if (x != curx) {
            // invariant: zero outstanding cp.async groups here
            if (curx >= 0) flush_rows(curx);
            load_tile64(sb + 0u, x * 64, tid);                 // A
            load_tile64(sb + OFF_B, tj * 64, tid);             // B into buffer 0
            if (tid < 4) cp16(sb + OFF_CLS + tid * 16u, g_clsb + tj * 64 + tid * 16);
            cp_commit();
            cp_wait0();
            __syncthreads();
            buf = 0;
            curx = x;
#pragma unroll
            for (int ri = 0; ri < 4; ++ri) {
                int row = warp_m * 32 + (ri >> 1) * 16 + (ri & 1) * 8 + (l >> 2);
                int cr = g_cls[x * 64 + row];
                pc[ri] = cr ^ 1;
                ncl[ri] = cr ^ 2;
            }
        }

        // prefetch next job's B only if it shares x
        bool pf = false;
        if (j + 1 < jend) {
            int nj = g_joblist[j + 1];
            if ((nj >> 8) == x) {
                int ntj = (x + (nj & 255)) & 127;
                load_tile64(sb + OFF_B + (uint32_t)(buf ^ 1) * 34816u, ntj * 64, tid);
                if (tid < 4)
                    cp16(sb + OFF_CLS + (uint32_t)(buf ^ 1) * 64u + tid * 16u,
                         g_clsb + ntj * 64 + tid * 16);
                cp_commit();
                cp_wait1();
                pf = true;
            }
        }
        if (!pf) cp_wait0();
        __syncthreads();

        // ---------------- MMA: 64x64 tile, K=128, 3 splits (identical to R10)
        const uint32_t pBh = sb + OFF_B + (uint32_t)buf * 34816u + laneB;
        const uint32_t pBl = pBh + ATILE;

        float acc[2][2][4];
#pragma unroll
        for (int mf = 0; mf < 2; ++mf)
#pragma unroll
            for (int nf = 0; nf < 2; ++nf)
#pragma unroll
                for (int c4 = 0; c4 < 4; ++c4) acc[mf][nf][c4] = 0.f;

#pragma unroll 1
        for (int ks = 0; ks < 8; ++ks) {
            const uint32_t ko = (uint32_t)ks * 32u;
            uint32_t aH[2][4], aL[2][4], bh[4], bl[4];
            ldsm4(aH[0], pAh + ko);
            ldsm4(aH[1], pAh + 16u * RSB + ko);
            ldsm4(aL[0], pAl + ko);
            ldsm4(aL[1], pAl + 16u * RSB + ko);
            ldsm4(bh, pBh + ko);
            ldsm4(bl, pBl + ko);
#pragma unroll
            for (int nf = 0; nf < 2; ++nf)
#pragma unroll
                for (int mf = 0; mf < 2; ++mf)
                    mma_bf16(acc[mf][nf], aH[mf], bh[nf], bh[nf + 2]);
#pragma unroll
            for (int nf = 0; nf < 2; ++nf)
#pragma unroll
                for (int mf = 0; mf < 2; ++mf)
                    mma_bf16(acc[mf][nf], aH[mf], bl[nf], bl[nf + 2]);
#pragma unroll
            for (int nf = 0; nf < 2; ++nf)
#pragma unroll
                for (int mf = 0; mf < 2; ++mf)
                    mma_bf16(acc[mf][nf], aL[mf], bh[nf], bh[nf + 2]);
        }

        // ---------------- epilogue (identical to R10)
        const float dc = (d != 0) ? 1.0f : 0.0f;
        const uint32_t clsb_s = sb + OFF_CLS + (uint32_t)buf * 64u +
                                (uint32_t)(warp_n * 16 + 2 * (l & 3));
#pragma unroll
        for (int nf = 0; nf < 2; ++nf) {
            unsigned short cw;
            asm volatile("ld.shared.u16 %0, [%1];" : "=h"(cw) : "r"(clsb_s + (uint32_t)nf * 8u));
            const int cj0 = cw & 0xff, cj1 = cw >> 8;
            float cE0 = 0.f, cE1 = 0.f, cN0 = 0.f, cN1 = 0.f, cL0 = 0.f, cL1 = 0.f;
#pragma unroll
            for (int ri = 0; ri < 4; ++ri) {
                float v0 = acc[ri >> 1][nf][(ri & 1) * 2 + 0];
                float v1 = acc[ri >> 1][nf][(ri & 1) * 2 + 1];
                float e0 = ex2f(v0), e1 = ex2f(v1);
                if (cj0 == pc[ri]) { epos[ri] += e0; lsum[ri] += v0;
                                     cE0 += dc * e0; cL0 += dc * v0; }
                else if (cj0 == ncl[ri]) { eneg[ri] += e0; cN0 += dc * e0; }
                if (cj1 == pc[ri]) { epos[ri] += e1; lsum[ri] += v1;
                                     cE1 += dc * e1; cL1 += dc * v1; }
                else if (cj1 == ncl[ri]) { eneg[ri] += e1; cN1 += dc * e1; }
            }
#pragma unroll
            for (int s = 4; s <= 16; s <<= 1) {
                cE0 += __shfl_xor_sync(0xffffffffu, cE0, s);
                cE1 += __shfl_xor_sync(0xffffffffu, cE1, s);
                cN0 += __shfl_xor_sync(0xffffffffu, cN0, s);
                cN1 += __shfl_xor_sync(0xffffffffu, cN1, s);
                cL0 += __shfl_xor_sync(0xffffffffu, cL0, s);
                cL1 += __shfl_xor_sync(0xffffffffu, cL1, s);
            }
            if ((l >> 2) == 0) {
                int col = warp_n * 16 + nf * 8 + 2 * l;
                int base = (warp_m * 64 + col) * 3;
                red[base + 0] = cE0; red[base + 1] = cN0; red[base + 2] = cL0;
                red[base + 3] = cE1; red[base + 4] = cN1; red[base + 5] = cL1;
            }
        }
        __syncthreads();
        if (d != 0 && tid < 64) {
            float E = red[tid * 3 + 0] + red[(64 + tid) * 3 + 0];
            float N = red[tid * 3 + 1] + red[(64 + tid) * 3 + 1];
            float L = red[tid * 3 + 2] + red[(64 + tid) * 3 + 2];
            g_cpart[d - 1][tj * 64 + tid] = make_float4(E, N, L, 0.f);
        }
        __syncthreads();
        if (pf) buf ^= 1;
    }

    if (curx >= 0) flush_rows(curx);
}

// ---------------------------------------------------------------- per-row values
// grid 128 x 256: 64 rows/CTA, 4 threads/row, 18 slices each (8 rpart + 64 cpart).
__global__ void rowval_kernel() {
    int tid = threadIdx.x;
    int i = blockIdx.x * 64 + (tid >> 2);
    int p = tid & 3;
    float Ep = 0.f, En = 0.f, Ls = 0.f;
#pragma unroll
    for (int s = 0; s < 18; ++s) {
        int sl = p * 18 + s;                 // 0..71
        float4 v = (sl < 8) ? g_rpart[sl][i] : g_cpart[sl - 8][i];
        Ep += v.x; En += v.y; Ls += v.z;
    }
#pragma unroll
    for (int o = 1; o <= 2; o <<= 1) {
        Ep += __shfl_xor_sync(0xffffffffu, Ep, o);
        En += __shfl_xor_sync(0xffffffffu, En, o);
        Ls += __shfl_xor_sync(0xffffffffu, Ls, o);
    }
    if (p == 0) {
        int ci = g_cls[i];
        int pcnt = g_cnt4[ci ^ 1];
        int ncnt = g_cnt4[ci ^ 2];
        float val = 0.f;
        if (pcnt > 0 && ncnt > 0)
            val = (Ls * 0.6931471805599453f - (float)pcnt * logf(Ep + En)) / (float)pcnt;
        g_rowval[i] = val;
    }
}

// ---------------------------------------------------------------- final sum
__global__ void sum_kernel(float* __restrict__ out) {
    __shared__ float s[256];
    float acc = 0.f;
    for (int i = threadIdx.x; i < B_SZ; i += 256) acc += g_rowval[i];
    s[threadIdx.x] = acc;
    __syncthreads();
    for (int o = 128; o; o >>= 1) {
        if (threadIdx.x < o) s[threadIdx.x] += s[threadIdx.x + o];
        __syncthreads();
    }
    if (threadIdx.x == 0) out[0] = -s[0] / (float)B_SZ;
}

// ---------------------------------------------------------------- launch
extern "C" void kernel_launch(void* const* d_in, const int* in_sizes, int n_in,
                              void* d_out, int out_size) {
    const float* F = (const float*)d_in[0];
    const void* dix = d_in[1];
    const void* tt  = d_in[2];
    const void* tp  = d_in[3];
    float* out = (float*)d_out;

    zero_kernel<<<512, 256>>>();
    detect_kernel<<<1, 256>>>((const long long*)dix);
    cls_kernel<<<32, 256>>>(dix, tt, tp);
    rank_kernel<<<1, 256>>>();
    joblist_kernel<<<1, 128>>>();
    prep_kernel<<<(B_SZ * 32) / 256, 256>>>(F);

    cudaFuncSetAttribute(main_kernel, cudaFuncAttributeMaxDynamicSharedMemorySize, SMEM_BYTES);
    main_kernel<<<NCTA, 256, SMEM_BYTES>>>();

    rowval_kernel<<<128, 256>>>();
    sum_kernel<<<1, 256>>>(out);
}

// round 13
// speedup vs baseline: 1.5465x; 1.1174x over previous
#include <cuda_runtime.h>
#include <cuda_bf16.h>
#include <cstdint>

// ContrastiveLoss B=8192 D=128 T=0.1, classes c=2*tt+tp in {0..3}
// Round 13: R12 + register-only rank_kernel (R12's was local-memory bound:
// lc[c]++ / off[c]++ with dynamic index -> LDL/STL chains, 25us) + gate the
// column-side shfl reduction on d!=0. Everything else identical to R12.

#define B_SZ 8192
#define RSB  272u
#define ATILE 17408u              // 64 rows * 272
#define OFF_B   34816u            // + buf*34816 ; hi +0, lo +17408
#define OFF_CLS 104448u           // + buf*64
#define OFF_RED 104576u           // 3072 B scratch
#define SMEM_BYTES (104576 + 3072 + 1024)
#define NCTA 256

// ---------------------------------------------------------------- globals
__device__ __align__(256) __nv_bfloat16 g_hi[B_SZ * 128];
__device__ __align__(256) __nv_bfloat16 g_lo[B_SZ * 128];
__device__ int           g_cls_orig[B_SZ];
__device__ int           g_newpos[B_SZ];
__device__ int           g_cls[B_SZ];
__device__ __align__(256) unsigned char g_clsb[B_SZ];
__device__ unsigned char g_blockcls[128];
__device__ int           g_cnt4[4];
__device__ int           g_joblist[8448];    // (x<<8)|d, grouped by x
__device__ int           g_njobs;
__device__ float4        g_rpart[8][B_SZ];   // row partials per CTA slot
__device__ float4        g_cpart[64][B_SZ];  // col partials per (d-1)
__device__ float         g_rowval[B_SZ];
__device__ int           g_is64;

// ---------------------------------------------------------------- helpers
__device__ __forceinline__ uint32_t smem_u32(const void* p) {
    uint32_t a;
    asm("{ .reg .u64 t; cvta.to.shared.u64 t, %1; cvt.u32.u64 %0, t; }" : "=r"(a) : "l"(p));
    return a;
}
__device__ __forceinline__ void cp16(uint32_t dst, const void* src) {
    asm volatile("cp.async.cg.shared.global [%0], [%1], 16;" :: "r"(dst), "l"(src) : "memory");
}
__device__ __forceinline__ void cp_commit() {
    asm volatile("cp.async.commit_group;" ::: "memory");
}
__device__ __forceinline__ void cp_wait0() {
    asm volatile("cp.async.wait_group 0;" ::: "memory");
}
__device__ __forceinline__ void cp_wait1() {
    asm volatile("cp.async.wait_group 1;" ::: "memory");
}
__device__ __forceinline__ void ldsm4(uint32_t* r, uint32_t addr) {
    asm volatile("ldmatrix.sync.aligned.m8n8.x4.shared.b16 {%0,%1,%2,%3}, [%4];"
                 : "=r"(r[0]), "=r"(r[1]), "=r"(r[2]), "=r"(r[3]) : "r"(addr));
}
__device__ __forceinline__ void mma_bf16(float* c, const uint32_t* a, uint32_t b0, uint32_t b1) {
    asm volatile(
        "mma.sync.aligned.m16n8k16.row.col.f32.bf16.bf16.f32 "
        "{%0,%1,%2,%3}, {%4,%5,%6,%7}, {%8,%9}, {%0,%1,%2,%3};"
        : "+f"(c[0]), "+f"(c[1]), "+f"(c[2]), "+f"(c[3])
        : "r"(a[0]), "r"(a[1]), "r"(a[2]), "r"(a[3]), "r"(b0), "r"(b1));
}
__device__ __forceinline__ float ex2f(float v) {
    float e;
    asm("ex2.approx.ftz.f32 %0, %1;" : "=f"(e) : "f"(v));
    return e;
}

__device__ __forceinline__ void load_tile64(uint32_t sdst_h, int rowbase, int tid) {
#pragma unroll
    for (int i = 0; i < 4; ++i) {
        int idx = tid + i * 256;
        int r = idx >> 4, c = idx & 15;
        uint32_t dst = sdst_h + (uint32_t)r * RSB + (uint32_t)c * 16u;
        cp16(dst, g_hi + (size_t)(rowbase + r) * 128 + c * 8);
        cp16(dst + ATILE, g_lo + (size_t)(rowbase + r) * 128 + c * 8);
    }
}

// ---------------------------------------------------------------- zero partials
__global__ void zero_kernel() {
    size_t n = (size_t)(64 + 8) * B_SZ;
    float4* cp = &g_cpart[0][0];
    float4* rp = &g_rpart[0][0];
    size_t idx = (size_t)blockIdx.x * blockDim.x + threadIdx.x;
    size_t stride = (size_t)gridDim.x * blockDim.x;
    for (size_t i = idx; i < n; i += stride) {
        if (i < (size_t)64 * B_SZ) cp[i] = make_float4(0.f, 0.f, 0.f, 0.f);
        else rp[i - (size_t)64 * B_SZ] = make_float4(0.f, 0.f, 0.f, 0.f);
    }
}

// ---------------------------------------------------------------- detect
__global__ void detect_kernel(const long long* __restrict__ dix64) {
    __shared__ int bad;
    if (threadIdx.x == 0) bad = 0;
    __syncthreads();
    int local = 0;
    for (int i = threadIdx.x; i < 4096; i += blockDim.x) {
        long long v = dix64[i];
        if (v < 0 || v >= 100000) local = 1;
    }
    if (local) atomicOr(&bad, 1);
    __syncthreads();
    if (threadIdx.x == 0) g_is64 = (bad == 0) ? 1 : 0;
}

// ---------------------------------------------------------------- classes (orig order)
__global__ void cls_kernel(const void* __restrict__ data_ix,
                           const void* __restrict__ tt,
                           const void* __restrict__ tp) {
    int i = blockIdx.x * 256 + threadIdx.x;
    int t, p;
    if (g_is64) {
        long long ix = ((const long long*)data_ix)[i];
        t = (int)((const long long*)tt)[ix];
        p = (int)((const long long*)tp)[ix];
    } else {
        int ix = ((const int*)data_ix)[i];
        t = ((const int*)tt)[ix];
        p = ((const int*)tp)[ix];
    }
    g_cls_orig[i] = t * 2 + p;
}

// ---------------------------------------------------------------- rank (register-only)
// FIX(R13): R12 used lc[c]++ / off[c]++ with dynamic c -> local memory LDL/STL
// chains (25us). Now: coalesced strided reads, 4 scalar counters via predicate
// adds, scatter offsets via select chains. Order within class changes (still a
// bijection; sums are permutation-invariant).
__global__ void rank_kernel() {
    __shared__ int wsum[4][8];
    __shared__ int tot_sh[4];
    int t = threadIdx.x, lane = t & 31, w = t >> 5;
    int cls_loc[32];
    int n0 = 0, n1 = 0, n2 = 0, n3 = 0;
#pragma unroll
    for (int r = 0; r < 32; ++r) {
        int c = g_cls_orig[t + 256 * r];    // coalesced
        cls_loc[r] = c;
        n0 += (c == 0); n1 += (c == 1); n2 += (c == 2); n3 += (c == 3);
    }
    int cnt[4] = {n0, n1, n2, n3};
    int ex[4];
#pragma unroll
    for (int c = 0; c < 4; ++c) {           // static index -> registers
        int v = cnt[c];
#pragma unroll
        for (int o = 1; o < 32; o <<= 1) {
            int u = __shfl_up_sync(0xffffffffu, v, o);
            if (lane >= o) v += u;
        }
        if (lane == 31) wsum[c][w] = v;
        ex[c] = v - cnt[c];
    }
    __syncthreads();
    if (t < 4) {
        int run = 0;
#pragma unroll
        for (int u = 0; u < 8; ++u) { int tmp = wsum[t][u]; wsum[t][u] = run; run += tmp; }
        tot_sh[t] = run;
        g_cnt4[t] = run;
    }
    __syncthreads();
    int b0 = 0;
    int b1 = tot_sh[0];
    int b2 = b1 + tot_sh[1];
    int b3 = b2 + tot_sh[2];
    int o0 = b0 + wsum[0][w] + ex[0];
    int o1 = b1 + wsum[1][w] + ex[1];
    int o2 = b2 + wsum[2][w] + ex[2];
    int o3 = b3 + wsum[3][w] + ex[3];
#pragma unroll
    for (int r = 0; r < 32; ++r) {
        int i = t + 256 * r;
        int c = cls_loc[r];
        int np = (c == 0) ? o0 : (c == 1) ? o1 : (c == 2) ? o2 : o3;
        o0 += (c == 0); o1 += (c == 1); o2 += (c == 2); o3 += (c == 3);
        g_newpos[i] = np;
        g_cls[np] = c;
        g_clsb[np] = (unsigned char)c;
    }
    __syncthreads();
    if (t < 128) {
        int c0 = g_cls[t * 64], c1 = g_cls[t * 64 + 63];
        g_blockcls[t] = (c0 == c1) ? (unsigned char)c0 : (unsigned char)255;
    }
}

// ---------------------------------------------------------------- job list (128 threads)
__global__ void joblist_kernel() {
    __shared__ int woff[4];
    int x = threadIdx.x;            // 0..127
    int lane = x & 31, w = x >> 5;
    int bcx = g_blockcls[x];
    int n = 0;
#pragma unroll 1
    for (int d = 0; d <= 64; ++d) {
        if (d == 64 && x >= 64) break;
        int tj = (x + d) & 127;
        int bcj = g_blockcls[tj];
        int xr = bcx ^ bcj;
        bool skip = (bcx < 4 && bcj < 4) && (xr != 1) && (xr != 2);
        if (!skip) ++n;
    }
    int v = n;
#pragma unroll
    for (int o = 1; o < 32; o <<= 1) {
        int u = __shfl_up_sync(0xffffffffu, v, o);
        if (lane >= o) v += u;
    }
    if (lane == 31) woff[w] = v;
    int ex = v - n;
    __syncthreads();
    if (x == 0) {
        int run = 0;
        for (int u = 0; u < 4; ++u) { int tmp = woff[u]; woff[u] = run; run += tmp; }
        g_njobs = run;
    }
    __syncthreads();
    int pos = woff[w] + ex;
#pragma unroll 1
    for (int d = 0; d <= 64; ++d) {
        if (d == 64 && x >= 64) break;
        int tj = (x + d) & 127;
        int bcj = g_blockcls[tj];
        int xr = bcx ^ bcj;
        bool skip = (bcx < 4 && bcj < 4) && (xr != 1) && (xr != 2);
        if (!skip) g_joblist[pos++] = (x << 8) | d;
    }
}

// ---------------------------------------------------------------- prep (normalize+split, scatter)
__global__ void prep_kernel(const float* __restrict__ F) {
    int warp = (blockIdx.x * blockDim.x + threadIdx.x) >> 5;
    int lane = threadIdx.x & 31;
    const float* row = F + (size_t)warp * 128;
    float v0 = row[lane], v1 = row[lane + 32], v2 = row[lane + 64], v3 = row[lane + 96];
    float ss = v0 * v0 + v1 * v1 + v2 * v2 + v3 * v3;
#pragma unroll
    for (int o = 16; o; o >>= 1) ss += __shfl_xor_sync(0xffffffffu, ss, o);
    float scale = sqrtf(14.4269504088896f) / sqrtf(ss);
    int np = g_newpos[warp];
    float g[4] = {v0 * scale, v1 * scale, v2 * scale, v3 * scale};
#pragma unroll
    for (int qq = 0; qq < 4; ++qq) {
        __nv_bfloat16 h = __float2bfloat16(g[qq]);
        __nv_bfloat16 lo = __float2bfloat16(g[qq] - __bfloat162float(h));
        g_hi[(size_t)np * 128 + lane + qq * 32] = h;
        g_lo[(size_t)np * 128 + lane + qq * 32] = lo;
    }
}

// ---------------------------------------------------------------- main kernel
__global__ void __launch_bounds__(256, 2) main_kernel() {
    extern __shared__ char smraw[];
    char* smp = (char*)(((uintptr_t)smraw + 1023) & ~(uintptr_t)1023);
    const uint32_t sb = smem_u32(smp);
    float* red = (float*)(smp + OFF_RED);

    const int tid = threadIdx.x;
    const int l = tid & 31, wid = tid >> 5;
    const int warp_m = wid >> 2, warp_n = wid & 3;
    const int cta = blockIdx.x;
    const int slot = cta & 7;

    const int M = g_njobs;
    const int jstart = (int)(((long long)cta * M) / NCTA);
    const int jend   = (int)(((long long)(cta + 1) * M) / NCTA);

    const uint32_t laneA = (uint32_t)((warp_m * 32 + (l & 15)) * (int)RSB + ((l >> 4) * 16));
    const uint32_t pAh = sb + laneA;
    const uint32_t pAl = sb + ATILE + laneA;
    const uint32_t laneB = (uint32_t)((warp_n * 16 + (l & 15)) * (int)RSB + ((l >> 4) * 16));

    float epos[4] = {0.f, 0.f, 0.f, 0.f};
    float eneg[4] = {0.f, 0.f, 0.f, 0.f};
    float lsum[4] = {0.f, 0.f, 0.f, 0.f};
    int pc[4], ncl[4];
    int curx = -1, buf = 0;

    auto flush_rows = [&](int fx) {
#pragma unroll
        for (int ri = 0; ri < 4; ++ri) {
            epos[ri] += __shfl_xor_sync(0xffffffffu, epos[ri], 1);
            epos[ri] += __shfl_xor_sync(0xffffffffu, epos[ri], 2);
            eneg[ri] += __shfl_xor_sync(0xffffffffu, eneg[ri], 1);
            eneg[ri] += __shfl_xor_sync(0xffffffffu, eneg[ri], 2);
            lsum[ri] += __shfl_xor_sync(0xffffffffu, lsum[ri], 1);
            lsum[ri] += __shfl_xor_sync(0xffffffffu, lsum[ri], 2);
        }
        if ((l & 3) == 0) {
#pragma unroll
            for (int ri = 0; ri < 4; ++ri) {
                int row = warp_m * 32 + (ri >> 1) * 16 + (ri & 1) * 8 + (l >> 2);
                red[(row * 4 + warp_n) * 3 + 0] = epos[ri];
                red[(row * 4 + warp_n) * 3 + 1] = eneg[ri];
                red[(row * 4 + warp_n) * 3 + 2] = lsum[ri];
            }
        }
        __syncthreads();
        if (tid < 64) {
            float Ep = 0.f, En = 0.f, Ls = 0.f;
#pragma unroll
            for (int wn = 0; wn < 4; ++wn) {
                Ep += red[(tid * 4 + wn) * 3 + 0];
                En += red[(tid * 4 + wn) * 3 + 1];
                Ls += red[(tid * 4 + wn) * 3 + 2];
            }
            g_rpart[slot][fx * 64 + tid] = make_float4(Ep, En, Ls, 0.f);
        }
        __syncthreads();
#pragma unroll
        for (int ri = 0; ri < 4; ++ri) { epos[ri] = 0.f; eneg[ri] = 0.f; lsum[ri] = 0.f; }
    };

    for (int j = jstart; j < jend; ++j) {
        const int job = g_joblist[j];
        const int x = job >> 8, d = job & 255;
        const int tj = (x + d) & 127;

        if (x != curx) {
            if (curx >= 0) flush_rows(curx);
            load_tile64(sb + 0u, x * 64, tid);                 // A
            load_tile64(sb + OFF_B, tj * 64, tid);             // B into buffer 0
            if (tid < 4) cp16(sb + OFF_CLS + tid * 16u, g_clsb + tj * 64 + tid * 16);
            cp_commit();
            cp_wait0();
            __syncthreads();
            buf = 0;
            curx = x;
#pragma unroll
            for (int ri = 0; ri < 4; ++ri) {
                int row = warp_m * 32 + (ri >> 1) * 16 + (ri & 1) * 8 + (l >> 2);
                int cr = g_cls[x * 64 + row];
                pc[ri] = cr ^ 1;
                ncl[ri] = cr ^ 2;
            }
        }

        bool pf = false;
        if (j + 1 < jend) {
            int nj = g_joblist[j + 1];
            if ((nj >> 8) == x) {
                int ntj = (x + (nj & 255)) & 127;
                load_tile64(sb + OFF_B + (uint32_t)(buf ^ 1) * 34816u, ntj * 64, tid);
                if (tid < 4)
                    cp16(sb + OFF_CLS + (uint32_t)(buf ^ 1) * 64u + tid * 16u,
                         g_clsb + ntj * 64 + tid * 16);
                cp_commit();
                cp_wait1();
                pf = true;
            }
        }
        if (!pf) cp_wait0();
        __syncthreads();

        // ---------------- MMA: 64x64 tile, K=128, 3 splits
        const uint32_t pBh = sb + OFF_B + (uint32_t)buf * 34816u + laneB;
        const uint32_t pBl = pBh + ATILE;

        float acc[2][2][4];
#pragma unroll
        for (int mf = 0; mf < 2; ++mf)
#pragma unroll
            for (int nf = 0; nf < 2; ++nf)
#pragma unroll
                for (int c4 = 0; c4 < 4; ++c4) acc[mf][nf][c4] = 0.f;

#pragma unroll 1
        for (int ks = 0; ks < 8; ++ks) {
            const uint32_t ko = (uint32_t)ks * 32u;
            uint32_t aH[2][4], aL[2][4], bh[4], bl[4];
            ldsm4(aH[0], pAh + ko);
            ldsm4(aH[1], pAh + 16u * RSB + ko);
            ldsm4(aL[0], pAl + ko);
            ldsm4(aL[1], pAl + 16u * RSB + ko);
            ldsm4(bh, pBh + ko);
            ldsm4(bl, pBl + ko);
#pragma unroll
            for (int nf = 0; nf < 2; ++nf)
#pragma unroll
                for (int mf = 0; mf < 2; ++mf)
                    mma_bf16(acc[mf][nf], aH[mf], bh[nf], bh[nf + 2]);
#pragma unroll
            for (int nf = 0; nf < 2; ++nf)
#pragma unroll
                for (int mf = 0; mf < 2; ++mf)
                    mma_bf16(acc[mf][nf], aH[mf], bl[nf], bl[nf + 2]);
#pragma unroll
            for (int nf = 0; nf < 2; ++nf)
#pragma unroll
                for (int mf = 0; mf < 2; ++mf)
                    mma_bf16(acc[mf][nf], aL[mf], bh[nf], bh[nf + 2]);
        }

        // ---------------- epilogue
        const uint32_t clsb_s = sb + OFF_CLS + (uint32_t)buf * 64u +
                                (uint32_t)(warp_n * 16 + 2 * (l & 3));
#pragma unroll
        for (int nf = 0; nf < 2; ++nf) {
            unsigned short cw;
            asm volatile("ld.shared.u16 %0, [%1];" : "=h"(cw) : "r"(clsb_s + (uint32_t)nf * 8u));
            const int cj0 = cw & 0xff, cj1 = cw >> 8;
            float cE0 = 0.f, cE1 = 0.f, cN0 = 0.f, cN1 = 0.f, cL0 = 0.f, cL1 = 0.f;
#pragma unroll
            for (int ri = 0; ri < 4; ++ri) {
                float v0 = acc[ri >> 1][nf][(ri & 1) * 2 + 0];
                float v1 = acc[ri >> 1][nf][(ri & 1) * 2 + 1];
                float e0 = ex2f(v0), e1 = ex2f(v1);
                if (cj0 == pc[ri]) { epos[ri] += e0; lsum[ri] += v0; cE0 += e0; cL0 += v0; }
                else if (cj0 == ncl[ri]) { eneg[ri] += e0; cN0 += e0; }
                if (cj1 == pc[ri]) { epos[ri] += e1; lsum[ri] += v1; cE1 += e1; cL1 += v1; }
                else if (cj1 == ncl[ri]) { eneg[ri] += e1; cN1 += e1; }
            }
            if (d != 0) {   // gate col-side reduction (d is CTA-uniform)
#pragma unroll
                for (int s = 4; s <= 16; s <<= 1) {
                    cE0 += __shfl_xor_sync(0xffffffffu, cE0, s);
                    cE1 += __shfl_xor_sync(0xffffffffu, cE1, s);
                    cN0 += __shfl_xor_sync(0xffffffffu, cN0, s);
                    cN1 += __shfl_xor_sync(0xffffffffu, cN1, s);
                    cL0 += __shfl_xor_sync(0xffffffffu, cL0, s);
                    cL1 += __shfl_xor_sync(0xffffffffu, cL1, s);
                }
                if ((l >> 2) == 0) {
                    int col = warp_n * 16 + nf * 8 + 2 * l;
                    int base = (warp_m * 64 + col) * 3;
                    red[base + 0] = cE0; red[base + 1] = cN0; red[base + 2] = cL0;
                    red[base + 3] = cE1; red[base + 4] = cN1; red[base + 5] = cL1;
                }
            }
        }
        __syncthreads();
        if (d != 0 && tid < 64) {
            float E = red[tid * 3 + 0] + red[(64 + tid) * 3 + 0];
            float N = red[tid * 3 + 1] + red[(64 + tid) * 3 + 1];
            float L = red[tid * 3 + 2] + red[(64 + tid) * 3 + 2];
            g_cpart[d - 1][tj * 64 + tid] = make_float4(E, N, L, 0.f);
        }
        __syncthreads();
        if (pf) buf ^= 1;
    }

    if (curx >= 0) flush_rows(curx);
}

// ---------------------------------------------------------------- per-row values
__global__ void rowval_kernel() {
    int tid = threadIdx.x;
    int i = blockIdx.x * 64 + (tid >> 2);
    int p = tid & 3;
    float Ep = 0.f, En = 0.f, Ls = 0.f;
#pragma unroll
    for (int s = 0; s < 18; ++s) {
        int sl = p * 18 + s;                 // 0..71
        float4 v = (sl < 8) ? g_rpart[sl][i] : g_cpart[sl - 8][i];
        Ep += v.x; En += v.y; Ls += v.z;
    }
#pragma unroll
    for (int o = 1; o <= 2; o <<= 1) {
        Ep += __shfl_xor_sync(0xffffffffu, Ep, o);
        En += __shfl_xor_sync(0xffffffffu, En, o);
        Ls += __shfl_xor_sync(0xffffffffu, Ls, o);
    }
    if (p == 0) {
        int ci = g_cls[i];
        int pcnt = g_cnt4[ci ^ 1];
        int ncnt = g_cnt4[ci ^ 2];
        float val = 0.f;
        if (pcnt > 0 && ncnt > 0)
            val = (Ls * 0.6931471805599453f - (float)pcnt * logf(Ep + En)) / (float)pcnt;
        g_rowval[i] = val;
    }
}

// ---------------------------------------------------------------- final sum
__global__ void sum_kernel(float* __restrict__ out) {
    __shared__ float s[256];
    float acc = 0.f;
    for (int i = threadIdx.x; i < B_SZ; i += 256) acc += g_rowval[i];
    s[threadIdx.x] = acc;
    __syncthreads();
    for (int o = 128; o; o >>= 1) {
        if (threadIdx.x < o) s[threadIdx.x] += s[threadIdx.x + o];
        __syncthreads();
    }
    if (threadIdx.x == 0) out[0] = -s[0] / (float)B_SZ;
}

// ---------------------------------------------------------------- launch
extern "C" void kernel_launch(void* const* d_in, const int* in_sizes, int n_in,
                              void* d_out, int out_size) {
    const float* F = (const float*)d_in[0];
    const void* dix = d_in[1];
    const void* tt  = d_in[2];
    const void* tp  = d_in[3];
    float* out = (float*)d_out;

    zero_kernel<<<512, 256>>>();
    detect_kernel<<<1, 256>>>((const long long*)dix);
    cls_kernel<<<32, 256>>>(dix, tt, tp);
    rank_kernel<<<1, 256>>>();
    joblist_kernel<<<1, 128>>>();
    prep_kernel<<<(B_SZ * 32) / 256, 256>>>(F);

    cudaFuncSetAttribute(main_kernel, cudaFuncAttributeMaxDynamicSharedMemorySize, SMEM_BYTES);
    main_kernel<<<NCTA, 256, SMEM_BYTES>>>();

    rowval_kernel<<<128, 256>>>();
    sum_kernel<<<1, 256>>>(out);
}

// round 14
// speedup vs baseline: 1.8664x; 1.2068x over previous
#include <cuda_runtime.h>
#include <cuda_bf16.h>
#include <cstdint>

// ContrastiveLoss B=8192 D=128 T=0.1, classes c=2*tt+tp in {0..3}
// Round 14: R13 + (1) multi-CTA deterministic counting sort (cls counts ->
// 4-warp scan -> ballot scatter), (2) zero folded into cls launch,
// (3) NCTA 256->296 (fill all 2-CTA/SM slots). Main MMA/epilogue unchanged.

#define B_SZ 8192
#define RSB  272u
#define ATILE 17408u              // 64 rows * 272
#define OFF_B   34816u            // + buf*34816 ; hi +0, lo +17408
#define OFF_CLS 104448u           // + buf*64
#define OFF_RED 104576u           // 3072 B scratch
#define SMEM_BYTES (104576 + 3072 + 1024)
#define NCTA 296

// ---------------------------------------------------------------- globals
__device__ __align__(256) __nv_bfloat16 g_hi[B_SZ * 128];
__device__ __align__(256) __nv_bfloat16 g_lo[B_SZ * 128];
__device__ int           g_cls_orig[B_SZ];
__device__ int           g_newpos[B_SZ];
__device__ int           g_cls[B_SZ];
__device__ __align__(256) unsigned char g_clsb[B_SZ];
__device__ int           g_blkcnt[32][4];
__device__ int           g_blkoff[32][4];
__device__ int           g_cnt4[4];
__device__ int           g_joblist[8448];    // (x<<8)|d, grouped by x
__device__ int           g_njobs;
__device__ float4        g_rpart[8][B_SZ];
__device__ float4        g_cpart[64][B_SZ];
__device__ float         g_rowval[B_SZ];
__device__ int           g_is64;

// ---------------------------------------------------------------- helpers
__device__ __forceinline__ uint32_t smem_u32(const void* p) {
    uint32_t a;
    asm("{ .reg .u64 t; cvta.to.shared.u64 t, %1; cvt.u32.u64 %0, t; }" : "=r"(a) : "l"(p));
    return a;
}
__device__ __forceinline__ void cp16(uint32_t dst, const void* src) {
    asm volatile("cp.async.cg.shared.global [%0], [%1], 16;" :: "r"(dst), "l"(src) : "memory");
}
__device__ __forceinline__ void cp_commit() {
    asm volatile("cp.async.commit_group;" ::: "memory");
}
__device__ __forceinline__ void cp_wait0() {
    asm volatile("cp.async.wait_group 0;" ::: "memory");
}
__device__ __forceinline__ void cp_wait1() {
    asm volatile("cp.async.wait_group 1;" ::: "memory");
}
__device__ __forceinline__ void ldsm4(uint32_t* r, uint32_t addr) {
    asm volatile("ldmatrix.sync.aligned.m8n8.x4.shared.b16 {%0,%1,%2,%3}, [%4];"
                 : "=r"(r[0]), "=r"(r[1]), "=r"(r[2]), "=r"(r[3]) : "r"(addr));
}
__device__ __forceinline__ void mma_bf16(float* c, const uint32_t* a, uint32_t b0, uint32_t b1) {
    asm volatile(
        "mma.sync.aligned.m16n8k16.row.col.f32.bf16.bf16.f32 "
        "{%0,%1,%2,%3}, {%4,%5,%6,%7}, {%8,%9}, {%0,%1,%2,%3};"
        : "+f"(c[0]), "+f"(c[1]), "+f"(c[2]), "+f"(c[3])
        : "r"(a[0]), "r"(a[1]), "r"(a[2]), "r"(a[3]), "r"(b0), "r"(b1));
}
__device__ __forceinline__ float ex2f(float v) {
    float e;
    asm("ex2.approx.ftz.f32 %0, %1;" : "=f"(e) : "f"(v));
    return e;
}

__device__ __forceinline__ void load_tile64(uint32_t sdst_h, int rowbase, int tid) {
#pragma unroll
    for (int i = 0; i < 4; ++i) {
        int idx = tid + i * 256;
        int r = idx >> 4, c = idx & 15;
        uint32_t dst = sdst_h + (uint32_t)r * RSB + (uint32_t)c * 16u;
        cp16(dst, g_hi + (size_t)(rowbase + r) * 128 + c * 8);
        cp16(dst + ATILE, g_lo + (size_t)(rowbase + r) * 128 + c * 8);
    }
}

// ---------------------------------------------------------------- detect
__global__ void detect_kernel(const long long* __restrict__ dix64) {
    __shared__ int bad;
    if (threadIdx.x == 0) bad = 0;
    __syncthreads();
    int local = 0;
    for (int i = threadIdx.x; i < 4096; i += blockDim.x) {
        long long v = dix64[i];
        if (v < 0 || v >= 100000) local = 1;
    }
    if (local) atomicOr(&bad, 1);
    __syncthreads();
    if (threadIdx.x == 0) g_is64 = (bad == 0) ? 1 : 0;
}

// ---------------------------------------------------------------- cls + counts + zero
// grid 288: blocks 0..31 compute classes + per-block class counts;
// blocks 32..287 zero the 72*B_SZ float4 partial buffers (2304 each).
__global__ void cls_zero_kernel(const void* __restrict__ data_ix,
                                const void* __restrict__ tt,
                                const void* __restrict__ tp) {
    int b = blockIdx.x, tid = threadIdx.x;
    if (b < 32) {
        __shared__ int hc[4];
        if (tid < 4) hc[tid] = 0;
        __syncthreads();
        int i = b * 256 + tid;
        int t, p;
        if (g_is64) {
            long long ix = ((const long long*)data_ix)[i];
            t = (int)((const long long*)tt)[ix];
            p = (int)((const long long*)tp)[ix];
        } else {
            int ix = ((const int*)data_ix)[i];
            t = ((const int*)tt)[ix];
            p = ((const int*)tp)[ix];
        }
        int c = t * 2 + p;
        g_cls_orig[i] = c;
        atomicAdd(&hc[c], 1);
        __syncthreads();
        if (tid < 4) g_blkcnt[b][tid] = hc[tid];
    } else {
        int bb = b - 32;                    // 0..255, 2304 float4 each
        float4* cp = &g_cpart[0][0];
        float4* rp = &g_rpart[0][0];
        const float4 z = make_float4(0.f, 0.f, 0.f, 0.f);
        for (int k = tid; k < 2304; k += 256) {
            size_t idx = (size_t)bb * 2304 + k;
            if (idx < (size_t)64 * B_SZ) cp[idx] = z;
            else rp[idx - (size_t)64 * B_SZ] = z;
        }
    }
}

// ---------------------------------------------------------------- scan (4 warps)
__global__ void scan_kernel() {
    __shared__ int tot[4];
    int tid = threadIdx.x, lane = tid & 31, w = tid >> 5;   // w = class
    int v = g_blkcnt[lane][w];
    int own = v;
#pragma unroll
    for (int o = 1; o < 32; o <<= 1) {
        int u = __shfl_up_sync(0xffffffffu, v, o);
        if (lane >= o) v += u;
    }
    int total = __shfl_sync(0xffffffffu, v, 31);
    if (lane == 0) { tot[w] = total; g_cnt4[w] = total; }
    __syncthreads();
    int base = 0;
    for (int c = 0; c < 4; ++c) base += (c < w) ? tot[c] : 0;
    g_blkoff[lane][w] = base + (v - own);
}

// ---------------------------------------------------------------- scatter (32 CTAs, ballot ranks)
__global__ void scatter_kernel() {
    __shared__ int wcnt[8][4];
    __shared__ int wbase[8][4];
    int b = blockIdx.x, tid = threadIdx.x, lane = tid & 31, w = tid >> 5;
    int i = b * 256 + tid;
    int c = g_cls_orig[i];
    unsigned b0 = __ballot_sync(0xffffffffu, c == 0);
    unsigned b1 = __ballot_sync(0xffffffffu, c == 1);
    unsigned b2 = __ballot_sync(0xffffffffu, c == 2);
    unsigned b3 = __ballot_sync(0xffffffffu, c == 3);
    unsigned mb = (c == 0) ? b0 : (c == 1) ? b1 : (c == 2) ? b2 : b3;
    int lanerank = __popc(mb & ((1u << lane) - 1u));
    if (lane == 0) {
        wcnt[w][0] = __popc(b0); wcnt[w][1] = __popc(b1);
        wcnt[w][2] = __popc(b2); wcnt[w][3] = __popc(b3);
    }
    __syncthreads();
    if (tid < 32) {
        int cc = tid >> 3, ww = tid & 7;
        int s = 0;
        for (int u = 0; u < ww; ++u) s += wcnt[u][cc];
        wbase[ww][cc] = s;
    }
    __syncthreads();
    int np = g_blkoff[b][c] + wbase[w][c] + lanerank;
    g_newpos[i] = np;
    g_cls[np] = c;
    g_clsb[np] = (unsigned char)c;
}

// ---------------------------------------------------------------- job list (+blockcls in smem)
__global__ void joblist_kernel() {
    __shared__ int woff[4];
    __shared__ unsigned char bc[128];
    int x = threadIdx.x;            // 0..127
    int lane = x & 31, w = x >> 5;
    {
        int c0 = g_cls[x * 64], c1 = g_cls[x * 64 + 63];
        bc[x] = (c0 == c1) ? (unsigned char)c0 : (unsigned char)255;
    }
    __syncthreads();
    int bcx = bc[x];
    int n = 0;
#pragma unroll 1
    for (int d = 0; d <= 64; ++d) {
        if (d == 64 && x >= 64) break;
        int tj = (x + d) & 127;
        int bcj = bc[tj];
        int xr = bcx ^ bcj;
        bool skip = (bcx < 4 && bcj < 4) && (xr != 1) && (xr != 2);
        if (!skip) ++n;
    }
    int v = n;
#pragma unroll
    for (int o = 1; o < 32; o <<= 1) {
        int u = __shfl_up_sync(0xffffffffu, v, o);
        if (lane >= o) v += u;
    }
    if (lane == 31) woff[w] = v;
    int ex = v - n;
    __syncthreads();
    if (x == 0) {
        int run = 0;
        for (int u = 0; u < 4; ++u) { int tmp = woff[u]; woff[u] = run; run += tmp; }
        g_njobs = run;
    }
    __syncthreads();
    int pos = woff[w] + ex;
#pragma unroll 1
    for (int d = 0; d <= 64; ++d) {
        if (d == 64 && x >= 64) break;
        int tj = (x + d) & 127;
        int bcj = bc[tj];
        int xr = bcx ^ bcj;
        bool skip = (bcx < 4 && bcj < 4) && (xr != 1) && (xr != 2);
        if (!skip) g_joblist[pos++] = (x << 8) | d;
    }
}

// ---------------------------------------------------------------- prep
__global__ void prep_kernel(const float* __restrict__ F) {
    int warp = (blockIdx.x * blockDim.x + threadIdx.x) >> 5;
    int lane = threadIdx.x & 31;
    const float* row = F + (size_t)warp * 128;
    float v0 = row[lane], v1 = row[lane + 32], v2 = row[lane + 64], v3 = row[lane + 96];
    float ss = v0 * v0 + v1 * v1 + v2 * v2 + v3 * v3;
#pragma unroll
    for (int o = 16; o; o >>= 1) ss += __shfl_xor_sync(0xffffffffu, ss, o);
    float scale = sqrtf(14.4269504088896f) / sqrtf(ss);
    int np = g_newpos[warp];
    float g[4] = {v0 * scale, v1 * scale, v2 * scale, v3 * scale};
#pragma unroll
    for (int qq = 0; qq < 4; ++qq) {
        __nv_bfloat16 h = __float2bfloat16(g[qq]);
        __nv_bfloat16 lo = __float2bfloat16(g[qq] - __bfloat162float(h));
        g_hi[(size_t)np * 128 + lane + qq * 32] = h;
        g_lo[(size_t)np * 128 + lane + qq * 32] = lo;
    }
}

// ---------------------------------------------------------------- main kernel
__global__ void __launch_bounds__(256, 2) main_kernel() {
    extern __shared__ char smraw[];
    char* smp = (char*)(((uintptr_t)smraw + 1023) & ~(uintptr_t)1023);
    const uint32_t sb = smem_u32(smp);
    float* red = (float*)(smp + OFF_RED);

    const int tid = threadIdx.x;
    const int l = tid & 31, wid = tid >> 5;
    const int warp_m = wid >> 2, warp_n = wid & 3;
    const int cta = blockIdx.x;
    const int slot = cta & 7;

    const int M = g_njobs;
    const int jstart = (int)(((long long)cta * M) / NCTA);
    const int jend   = (int)(((long long)(cta + 1) * M) / NCTA);

    const uint32_t laneA = (uint32_t)((warp_m * 32 + (l & 15)) * (int)RSB + ((l >> 4) * 16));
    const uint32_t pAh = sb + laneA;
    const uint32_t pAl = sb + ATILE + laneA;
    const uint32_t laneB = (uint32_t)((warp_n * 16 + (l & 15)) * (int)RSB + ((l >> 4) * 16));

    float epos[4] = {0.f, 0.f, 0.f, 0.f};
    float eneg[4] = {0.f, 0.f, 0.f, 0.f};
    float lsum[4] = {0.f, 0.f, 0.f, 0.f};
    int pc[4], ncl[4];
    int curx = -1, buf = 0;

    auto flush_rows = [&](int fx) {
#pragma unroll
        for (int ri = 0; ri < 4; ++ri) {
            epos[ri] += __shfl_xor_sync(0xffffffffu, epos[ri], 1);
            epos[ri] += __shfl_xor_sync(0xffffffffu, epos[ri], 2);
            eneg[ri] += __shfl_xor_sync(0xffffffffu, eneg[ri], 1);
            eneg[ri] += __shfl_xor_sync(0xffffffffu, eneg[ri], 2);
            lsum[ri] += __shfl_xor_sync(0xffffffffu, lsum[ri], 1);
            lsum[ri] += __shfl_xor_sync(0xffffffffu, lsum[ri], 2);
        }
        if ((l & 3) == 0) {
#pragma unroll
            for (int ri = 0; ri < 4; ++ri) {
                int row = warp_m * 32 + (ri >> 1) * 16 + (ri & 1) * 8 + (l >> 2);
                red[(row * 4 + warp_n) * 3 + 0] = epos[ri];
                red[(row * 4 + warp_n) * 3 + 1] = eneg[ri];
                red[(row * 4 + warp_n) * 3 + 2] = lsum[ri];
            }
        }
        __syncthreads();
        if (tid < 64) {
            float Ep = 0.f, En = 0.f, Ls = 0.f;
#pragma unroll
            for (int wn = 0; wn < 4; ++wn) {
                Ep += red[(tid * 4 + wn) * 3 + 0];
                En += red[(tid * 4 + wn) * 3 + 1];
                Ls += red[(tid * 4 + wn) * 3 + 2];
            }
            g_rpart[slot][fx * 64 + tid] = make_float4(Ep, En, Ls, 0.f);
        }
        __syncthreads();
#pragma unroll
        for (int ri = 0; ri < 4; ++ri) { epos[ri] = 0.f; eneg[ri] = 0.f; lsum[ri] = 0.f; }
    };

    for (int j = jstart; j < jend; ++j) {
        const int job = g_joblist[j];
        const int x = job >> 8, d = job & 255;
        const int tj = (x + d) & 127;

        if (x != curx) {
            if (curx >= 0) flush_rows(curx);
            load_tile64(sb + 0u, x * 64, tid);                 // A
            load_tile64(sb + OFF_B, tj * 64, tid);             // B into buffer 0
            if (tid < 4) cp16(sb + OFF_CLS + tid * 16u, g_clsb + tj * 64 + tid * 16);
            cp_commit();
            cp_wait0();
            __syncthreads();
            buf = 0;
            curx = x;
#pragma unroll
            for (int ri = 0; ri < 4; ++ri) {
                int row = warp_m * 32 + (ri >> 1) * 16 + (ri & 1) * 8 + (l >> 2);
                int cr = g_cls[x * 64 + row];
                pc[ri] = cr ^ 1;
                ncl[ri] = cr ^ 2;
            }
        }

        bool pf = false;
        if (j + 1 < jend) {
            int nj = g_joblist[j + 1];
            if ((nj >> 8) == x) {
                int ntj = (x + (nj & 255)) & 127;
                load_tile64(sb + OFF_B + (uint32_t)(buf ^ 1) * 34816u, ntj * 64, tid);
                if (tid < 4)
                    cp16(sb + OFF_CLS + (uint32_t)(buf ^ 1) * 64u + tid * 16u,
                         g_clsb + ntj * 64 + tid * 16);
                cp_commit();
                cp_wait1();
                pf = true;
            }
        }
        if (!pf) cp_wait0();
        __syncthreads();

        // ---------------- MMA: 64x64 tile, K=128, 3 splits
        const uint32_t pBh = sb + OFF_B + (uint32_t)buf * 34816u + laneB;
        const uint32_t pBl = pBh + ATILE;

        float acc[2][2][4];
#pragma unroll
        for (int mf = 0; mf < 2; ++mf)
#pragma unroll
            for (int nf = 0; nf < 2; ++nf)
#pragma unroll
                for (int c4 = 0; c4 < 4; ++c4) acc[mf][nf][c4] = 0.f;

#pragma unroll 1
        for (int ks = 0; ks < 8; ++ks) {
            const uint32_t ko = (uint32_t)ks * 32u;
            uint32_t aH[2][4], aL[2][4], bh[4], bl[4];
            ldsm4(aH[0], pAh + ko);
            ldsm4(aH[1], pAh + 16u * RSB + ko);
            ldsm4(aL[0], pAl + ko);
            ldsm4(aL[1], pAl + 16u * RSB + ko);
            ldsm4(bh, pBh + ko);
            ldsm4(bl, pBl + ko);
#pragma unroll
            for (int nf = 0; nf < 2; ++nf)
#pragma unroll
                for (int mf = 0; mf < 2; ++mf)
                    mma_bf16(acc[mf][nf], aH[mf], bh[nf], bh[nf + 2]);
#pragma unroll
            for (int nf = 0; nf < 2; ++nf)
#pragma unroll
                for (int mf = 0; mf < 2; ++mf)
                    mma_bf16(acc[mf][nf], aH[mf], bl[nf], bl[nf + 2]);
#pragma unroll
            for (int nf = 0; nf < 2; ++nf)
#pragma unroll
                for (int mf = 0; mf < 2; ++mf)
                    mma_bf16(acc[mf][nf], aL[mf], bh[nf], bh[nf + 2]);
        }

        // ---------------- epilogue
        const uint32_t clsb_s = sb + OFF_CLS + (uint32_t)buf * 64u +
                                (uint32_t)(warp_n * 16 + 2 * (l & 3));
#pragma unroll
        for (int nf = 0; nf < 2; ++nf) {
            unsigned short cw;
            asm volatile("ld.shared.u16 %0, [%1];" : "=h"(cw) : "r"(clsb_s + (uint32_t)nf * 8u));
            const int cj0 = cw & 0xff, cj1 = cw >> 8;
            float cE0 = 0.f, cE1 = 0.f, cN0 = 0.f, cN1 = 0.f, cL0 = 0.f, cL1 = 0.f;
#pragma unroll
            for (int ri = 0; ri < 4; ++ri) {
                float v0 = acc[ri >> 1][nf][(ri & 1) * 2 + 0];
                float v1 = acc[ri >> 1][nf][(ri & 1) * 2 + 1];
                float e0 = ex2f(v0), e1 = ex2f(v1);
                if (cj0 == pc[ri]) { epos[ri] += e0; lsum[ri] += v0; cE0 += e0; cL0 += v0; }
                else if (cj0 == ncl[ri]) { eneg[ri] += e0; cN0 += e0; }
                if (cj1 == pc[ri]) { epos[ri] += e1; lsum[ri] += v1; cE1 += e1; cL1 += v1; }
                else if (cj1 == ncl[ri]) { eneg[ri] += e1; cN1 += e1; }
            }
            if (d != 0) {
#pragma unroll
                for (int s = 4; s <= 16; s <<= 1) {
                    cE0 += __shfl_xor_sync(0xffffffffu, cE0, s);
                    cE1 += __shfl_xor_sync(0xffffffffu, cE1, s);
                    cN0 += __shfl_xor_sync(0xffffffffu, cN0, s);
                    cN1 += __shfl_xor_sync(0xffffffffu, cN1, s);
                    cL0 += __shfl_xor_sync(0xffffffffu, cL0, s);
                    cL1 += __shfl_xor_sync(0xffffffffu, cL1, s);
                }
                if ((l >> 2) == 0) {
                    int col = warp_n * 16 + nf * 8 + 2 * l;
                    int base = (warp_m * 64 + col) * 3;
                    red[base + 0] = cE0; red[base + 1] = cN0; red[base + 2] = cL0;
                    red[base + 3] = cE1; red[base + 4] = cN1; red[base + 5] = cL1;
                }
            }
        }
        __syncthreads();
        if (d != 0 && tid < 64) {
            float E = red[tid * 3 + 0] + red[(64 + tid) * 3 + 0];
            float N = red[tid * 3 + 1] + red[(64 + tid) * 3 + 1];
            float L = red[tid * 3 + 2] + red[(64 + tid) * 3 + 2];
            g_cpart[d - 1][tj * 64 + tid] = make_float4(E, N, L, 0.f);
        }
        __syncthreads();
        if (pf) buf ^= 1;
    }

    if (curx >= 0) flush_rows(curx);
}

// ---------------------------------------------------------------- per-row values
__global__ void rowval_kernel() {
    int tid = threadIdx.x;
    int i = blockIdx.x * 64 + (tid >> 2);
    int p = tid & 3;
    float Ep = 0.f, En = 0.f, Ls = 0.f;
#pragma unroll
    for (int s = 0; s < 18; ++s) {
        int sl = p * 18 + s;                 // 0..71
        float4 v = (sl < 8) ? g_rpart[sl][i] : g_cpart[sl - 8][i];
        Ep += v.x; En += v.y; Ls += v.z;
    }
#pragma unroll
    for (int o = 1; o <= 2; o <<= 1) {
        Ep += __shfl_xor_sync(0xffffffffu, Ep, o);
        En += __shfl_xor_sync(0xffffffffu, En, o);
        Ls += __shfl_xor_sync(0xffffffffu, Ls, o);
    }
    if (p == 0) {
        int ci = g_cls[i];
        int pcnt = g_cnt4[ci ^ 1];
        int ncnt = g_cnt4[ci ^ 2];
        float val = 0.f;
        if (pcnt > 0 && ncnt > 0)
            val = (Ls * 0.6931471805599453f - (float)pcnt * logf(Ep + En)) / (float)pcnt;
        g_rowval[i] = val;
    }
}

// ---------------------------------------------------------------- final sum
__global__ void sum_kernel(float* __restrict__ out) {
    __shared__ float s[256];
    float acc = 0.f;
    for (int i = threadIdx.x; i < B_SZ; i += 256) acc += g_rowval[i];
    s[threadIdx.x] = acc;
    __syncthreads();
    for (int o = 128; o; o >>= 1) {
        if (threadIdx.x < o) s[threadIdx.x] += s[threadIdx.x + o];
        __syncthreads();
    }
    if (threadIdx.x == 0) out[0] = -s[0] / (float)B_SZ;
}

// ---------------------------------------------------------------- launch
extern "C" void kernel_launch(void* const* d_in, const int* in_sizes, int n_in,
                              void* d_out, int out_size) {
    const float* F = (const float*)d_in[0];
    const void* dix = d_in[1];
    const void* tt  = d_in[2];
    const void* tp  = d_in[3];
    float* out = (float*)d_out;

    detect_kernel<<<1, 256>>>((const long long*)dix);
    cls_zero_kernel<<<288, 256>>>(dix, tt, tp);
    scan_kernel<<<1, 128>>>();
    scatter_kernel<<<32, 256>>>();
    joblist_kernel<<<1, 128>>>();
    prep_kernel<<<(B_SZ * 32) / 256, 256>>>(F);

    cudaFuncSetAttribute(main_kernel, cudaFuncAttributeMaxDynamicSharedMemorySize, SMEM_BYTES);
    main_kernel<<<NCTA, 256, SMEM_BYTES>>>();

    rowval_kernel<<<128, 256>>>();
    sum_kernel<<<1, 256>>>(out);
}

// round 15
// speedup vs baseline: 1.9325x; 1.0354x over previous
#include <cuda_runtime.h>
#include <cuda_bf16.h>
#include <cstdint>

// ContrastiveLoss B=8192 D=128 T=0.1, classes c=2*tt+tp in {0..3}
// Round 15: R14 with launch fusion 9 -> 5 kernels:
//   cls_zero (+local int-width detect), scatter (+inlined scan),
//   prep (+joblist in extra block), main (unchanged), rowval (+ticketed sum).

#define B_SZ 8192
#define RSB  272u
#define ATILE 17408u              // 64 rows * 272
#define OFF_B   34816u            // + buf*34816 ; hi +0, lo +17408
#define OFF_CLS 104448u           // + buf*64
#define OFF_RED 104576u           // 3072 B scratch
#define SMEM_BYTES (104576 + 3072 + 1024)
#define NCTA 296

// ---------------------------------------------------------------- globals
__device__ __align__(256) __nv_bfloat16 g_hi[B_SZ * 128];
__device__ __align__(256) __nv_bfloat16 g_lo[B_SZ * 128];
__device__ int           g_cls_orig[B_SZ];
__device__ int           g_newpos[B_SZ];
__device__ int           g_cls[B_SZ];
__device__ __align__(256) unsigned char g_clsb[B_SZ];
__device__ int           g_blkcnt[32][4];
__device__ int           g_cnt4[4];
__device__ int           g_joblist[8448];    // (x<<8)|d, grouped by x
__device__ int           g_njobs;
__device__ float4        g_rpart[8][B_SZ];
__device__ float4        g_cpart[64][B_SZ];
__device__ float         g_rowval[B_SZ];
__device__ int           g_ticket;

// ---------------------------------------------------------------- helpers
__device__ __forceinline__ uint32_t smem_u32(const void* p) {
    uint32_t a;
    asm("{ .reg .u64 t; cvta.to.shared.u64 t, %1; cvt.u32.u64 %0, t; }" : "=r"(a) : "l"(p));
    return a;
}
__device__ __forceinline__ void cp16(uint32_t dst, const void* src) {
    asm volatile("cp.async.cg.shared.global [%0], [%1], 16;" :: "r"(dst), "l"(src) : "memory");
}
__device__ __forceinline__ void cp_commit() {
    asm volatile("cp.async.commit_group;" ::: "memory");
}
__device__ __forceinline__ void cp_wait0() {
    asm volatile("cp.async.wait_group 0;" ::: "memory");
}
__device__ __forceinline__ void cp_wait1() {
    asm volatile("cp.async.wait_group 1;" ::: "memory");
}
__device__ __forceinline__ void ldsm4(uint32_t* r, uint32_t addr) {
    asm volatile("ldmatrix.sync.aligned.m8n8.x4.shared.b16 {%0,%1,%2,%3}, [%4];"
                 : "=r"(r[0]), "=r"(r[1]), "=r"(r[2]), "=r"(r[3]) : "r"(addr));
}
__device__ __forceinline__ void mma_bf16(float* c, const uint32_t* a, uint32_t b0, uint32_t b1) {
    asm volatile(
        "mma.sync.aligned.m16n8k16.row.col.f32.bf16.bf16.f32 "
        "{%0,%1,%2,%3}, {%4,%5,%6,%7}, {%8,%9}, {%0,%1,%2,%3};"
        : "+f"(c[0]), "+f"(c[1]), "+f"(c[2]), "+f"(c[3])
        : "r"(a[0]), "r"(a[1]), "r"(a[2]), "r"(a[3]), "r"(b0), "r"(b1));
}
__device__ __forceinline__ float ex2f(float v) {
    float e;
    asm("ex2.approx.ftz.f32 %0, %1;" : "=f"(e) : "f"(v));
    return e;
}

__device__ __forceinline__ void load_tile64(uint32_t sdst_h, int rowbase, int tid) {
#pragma unroll
    for (int i = 0; i < 4; ++i) {
        int idx = tid + i * 256;
        int r = idx >> 4, c = idx & 15;
        uint32_t dst = sdst_h + (uint32_t)r * RSB + (uint32_t)c * 16u;
        cp16(dst, g_hi + (size_t)(rowbase + r) * 128 + c * 8);
        cp16(dst + ATILE, g_lo + (size_t)(rowbase + r) * 128 + c * 8);
    }
}

// ---------------------------------------------------------------- cls + counts + zero (+detect)
// grid 288: blocks 0..31: local int-width detect + classes + per-block counts;
// blocks 32..287: zero 72*B_SZ float4 partials (2304 each). Block 32 zeroes ticket.
__global__ void cls_zero_kernel(const void* __restrict__ data_ix,
                                const void* __restrict__ tt,
                                const void* __restrict__ tp) {
    int b = blockIdx.x, tid = threadIdx.x;
    if (b < 32) {
        __shared__ int hc[4];
        __shared__ int bad;
        if (tid < 4) hc[tid] = 0;
        if (tid == 0) bad = 0;
        __syncthreads();
        // local detect: window of 256 int64 within the first 4096 (safe either way)
        {
            long long v = ((const long long*)data_ix)[(b & 15) * 256 + tid];
            if (v < 0 || v >= 100000) atomicOr(&bad, 1);
        }
        __syncthreads();
        const bool is64 = (bad == 0);
        int i = b * 256 + tid;
        int t, p;
        if (is64) {
            long long ix = ((const long long*)data_ix)[i];
            t = (int)((const long long*)tt)[ix];
            p = (int)((const long long*)tp)[ix];
        } else {
            int ix = ((const int*)data_ix)[i];
            t = ((const int*)tt)[ix];
            p = ((const int*)tp)[ix];
        }
        int c = t * 2 + p;
        g_cls_orig[i] = c;
        atomicAdd(&hc[c], 1);
        __syncthreads();
        if (tid < 4) g_blkcnt[b][tid] = hc[tid];
    } else {
        int bb = b - 32;                    // 0..255, 2304 float4 each
        if (bb == 0 && tid == 0) g_ticket = 0;
        float4* cp = &g_cpart[0][0];
        float4* rp = &g_rpart[0][0];
        const float4 z = make_float4(0.f, 0.f, 0.f, 0.f);
        for (int k = tid; k < 2304; k += 256) {
            size_t idx = (size_t)bb * 2304 + k;
            if (idx < (size_t)64 * B_SZ) cp[idx] = z;
            else rp[idx - (size_t)64 * B_SZ] = z;
        }
    }
}

// ---------------------------------------------------------------- scatter (+inlined scan)
// 32 CTAs; each CTA redundantly computes the identical 32x4 prefix in smem.
__global__ void scatter_kernel() {
    __shared__ int blkoff[32][4];
    __shared__ int wcnt[8][4];
    __shared__ int wbase[8][4];
    int b = blockIdx.x, tid = threadIdx.x, lane = tid & 31, w = tid >> 5;

    if (tid < 128) {                      // inlined scan: lane=block, w2=class
        int w2 = tid >> 5;                // 0..3
        int v = g_blkcnt[lane][w2];
        int own = v;
#pragma unroll
        for (int o = 1; o < 32; o <<= 1) {
            int u = __shfl_up_sync(0xffffffffu, v, o);
            if (lane >= o) v += u;
        }
        int total = __shfl_sync(0xffffffffu, v, 31);
        // class base needs totals of lower classes: share via smem
        wcnt[0][w2] = total;              // temporarily park totals
        __syncthreads();
        int base = 0;
        for (int c = 0; c < 4; ++c) base += (c < w2) ? wcnt[0][c] : 0;
        blkoff[lane][w2] = base + (v - own);
        if (lane == 0 && b == 0) g_cnt4[w2] = total;
    } else {
        __syncthreads();
    }
    __syncthreads();

    int i = b * 256 + tid;
    int c = g_cls_orig[i];
    unsigned b0 = __ballot_sync(0xffffffffu, c == 0);
    unsigned b1 = __ballot_sync(0xffffffffu, c == 1);
    unsigned b2 = __ballot_sync(0xffffffffu, c == 2);
    unsigned b3 = __ballot_sync(0xffffffffu, c == 3);
    unsigned mb = (c == 0) ? b0 : (c == 1) ? b1 : (c == 2) ? b2 : b3;
    int lanerank = __popc(mb & ((1u << lane) - 1u));
    if (lane == 0) {
        wcnt[w][0] = __popc(b0); wcnt[w][1] = __popc(b1);
        wcnt[w][2] = __popc(b2); wcnt[w][3] = __popc(b3);
    }
    __syncthreads();
    if (tid < 32) {
        int cc = tid >> 3, ww = tid & 7;
        int s = 0;
        for (int u = 0; u < ww; ++u) s += wcnt[u][cc];
        wbase[ww][cc] = s;
    }
    __syncthreads();
    int np = blkoff[b][c] + wbase[w][c] + lanerank;
    g_newpos[i] = np;
    g_cls[np] = c;
    g_clsb[np] = (unsigned char)c;
}

// ---------------------------------------------------------------- prep (+joblist in block 1024)
__global__ void prep_joblist_kernel(const float* __restrict__ F) {
    if (blockIdx.x == 1024) {
        // joblist: 128 active threads
        __shared__ int woff[4];
        __shared__ unsigned char bc[128];
        int x = threadIdx.x;
        if (x >= 128) return;
        int lane = x & 31, w = x >> 5;
        {
            int c0 = g_cls[x * 64], c1 = g_cls[x * 64 + 63];
            bc[x] = (c0 == c1) ? (unsigned char)c0 : (unsigned char)255;
        }
        __syncwarp();
        asm volatile("bar.sync 1, 128;" ::: "memory");
        int bcx = bc[x];
        int n = 0;
#pragma unroll 1
        for (int d = 0; d <= 64; ++d) {
            if (d == 64 && x >= 64) break;
            int tj = (x + d) & 127;
            int bcj = bc[tj];
            int xr = bcx ^ bcj;
            bool skip = (bcx < 4 && bcj < 4) && (xr != 1) && (xr != 2);
            if (!skip) ++n;
        }
        int v = n;
#pragma unroll
        for (int o = 1; o < 32; o <<= 1) {
            int u = __shfl_up_sync(0xffffffffu, v, o);
            if (lane >= o) v += u;
        }
        if (lane == 31) woff[w] = v;
        int ex = v - n;
        asm volatile("bar.sync 1, 128;" ::: "memory");
        if (x == 0) {
            int run = 0;
            for (int u = 0; u < 4; ++u) { int tmp = woff[u]; woff[u] = run; run += tmp; }
            g_njobs = run;
        }
        asm volatile("bar.sync 1, 128;" ::: "memory");
        int pos = woff[w] + ex;
#pragma unroll 1
        for (int d = 0; d <= 64; ++d) {
            if (d == 64 && x >= 64) break;
            int tj = (x + d) & 127;
            int bcj = bc[tj];
            int xr = bcx ^ bcj;
            bool skip = (bcx < 4 && bcj < 4) && (xr != 1) && (xr != 2);
            if (!skip) g_joblist[pos++] = (x << 8) | d;
        }
        return;
    }
    // prep: blocks 0..1023, 8 rows each
    int warp = (blockIdx.x * blockDim.x + threadIdx.x) >> 5;
    int lane = threadIdx.x & 31;
    const float* row = F + (size_t)warp * 128;
    float v0 = row[lane], v1 = row[lane + 32], v2 = row[lane + 64], v3 = row[lane + 96];
    float ss = v0 * v0 + v1 * v1 + v2 * v2 + v3 * v3;
#pragma unroll
    for (int o = 16; o; o >>= 1) ss += __shfl_xor_sync(0xffffffffu, ss, o);
    float scale = sqrtf(14.4269504088896f) / sqrtf(ss);
    int np = g_newpos[warp];
    float g[4] = {v0 * scale, v1 * scale, v2 * scale, v3 * scale};
#pragma unroll
    for (int qq = 0; qq < 4; ++qq) {
        __nv_bfloat16 h = __float2bfloat16(g[qq]);
        __nv_bfloat16 lo = __float2bfloat16(g[qq] - __bfloat162float(h));
        g_hi[(size_t)np * 128 + lane + qq * 32] = h;
        g_lo[(size_t)np * 128 + lane + qq * 32] = lo;
    }
}

// ---------------------------------------------------------------- main kernel (unchanged from R14)
__global__ void __launch_bounds__(256, 2) main_kernel() {
    extern __shared__ char smraw[];
    char* smp = (char*)(((uintptr_t)smraw + 1023) & ~(uintptr_t)1023);
    const uint32_t sb = smem_u32(smp);
    float* red = (float*)(smp + OFF_RED);

    const int tid = threadIdx.x;
    const int l = tid & 31, wid = tid >> 5;
    const int warp_m = wid >> 2, warp_n = wid & 3;
    const int cta = blockIdx.x;
    const int slot = cta & 7;

    const int M = g_njobs;
    const int jstart = (int)(((long long)cta * M) / NCTA);
    const int jend   = (int)(((long long)(cta + 1) * M) / NCTA);

    const uint32_t laneA = (uint32_t)((warp_m * 32 + (l & 15)) * (int)RSB + ((l >> 4) * 16));
    const uint32_t pAh = sb + laneA;
    const uint32_t pAl = sb + ATILE + laneA;
    const uint32_t laneB = (uint32_t)((warp_n * 16 + (l & 15)) * (int)RSB + ((l >> 4) * 16));

    float epos[4] = {0.f, 0.f, 0.f, 0.f};
    float eneg[4] = {0.f, 0.f, 0.f, 0.f};
    float lsum[4] = {0.f, 0.f, 0.f, 0.f};
    int pc[4], ncl[4];
    int curx = -1, buf = 0;

    auto flush_rows = [&](int fx) {
#pragma unroll
        for (int ri = 0; ri < 4; ++ri) {
            epos[ri] += __shfl_xor_sync(0xffffffffu, epos[ri], 1);
            epos[ri] += __shfl_xor_sync(0xffffffffu, epos[ri], 2);
            eneg[ri] += __shfl_xor_sync(0xffffffffu, eneg[ri], 1);
            eneg[ri] += __shfl_xor_sync(0xffffffffu, eneg[ri], 2);
            lsum[ri] += __shfl_xor_sync(0xffffffffu, lsum[ri], 1);
            lsum[ri] += __shfl_xor_sync(0xffffffffu, lsum[ri], 2);
        }
        if ((l & 3) == 0) {
#pragma unroll
            for (int ri = 0; ri < 4; ++ri) {
                int row = warp_m * 32 + (ri >> 1) * 16 + (ri & 1) * 8 + (l >> 2);
                red[(row * 4 + warp_n) * 3 + 0] = epos[ri];
                red[(row * 4 + warp_n) * 3 + 1] = eneg[ri];
                red[(row * 4 + warp_n) * 3 + 2] = lsum[ri];
            }
        }
        __syncthreads();
        if (tid < 64) {
            float Ep = 0.f, En = 0.f, Ls = 0.f;
#pragma unroll
            for (int wn = 0; wn < 4; ++wn) {
                Ep += red[(tid * 4 + wn) * 3 + 0];
                En += red[(tid * 4 + wn) * 3 + 1];
                Ls += red[(tid * 4 + wn) * 3 + 2];
            }
            g_rpart[slot][fx * 64 + tid] = make_float4(Ep, En, Ls, 0.f);
        }
        __syncthreads();
#pragma unroll
        for (int ri = 0; ri < 4; ++ri) { epos[ri] = 0.f; eneg[ri] = 0.f; lsum[ri] = 0.f; }
    };

    for (int j = jstart; j < jend; ++j) {
        const int job = g_joblist[j];
        const int x = job >> 8, d = job & 255;
        const int tj = (x + d) & 127;

        if (x != curx) {
            if (curx >= 0) flush_rows(curx);
            load_tile64(sb + 0u, x * 64, tid);
            load_tile64(sb + OFF_B, tj * 64, tid);
            if (tid < 4) cp16(sb + OFF_CLS + tid * 16u, g_clsb + tj * 64 + tid * 16);
            cp_commit();
            cp_wait0();
            __syncthreads();
            buf = 0;
            curx = x;
#pragma unroll
            for (int ri = 0; ri < 4; ++ri) {
                int row = warp_m * 32 + (ri >> 1) * 16 + (ri & 1) * 8 + (l >> 2);
                int cr = g_cls[x * 64 + row];
                pc[ri] = cr ^ 1;
                ncl[ri] = cr ^ 2;
            }
        }

        bool pf = false;
        if (j + 1 < jend) {
            int nj = g_joblist[j + 1];
            if ((nj >> 8) == x) {
                int ntj = (x + (nj & 255)) & 127;
                load_tile64(sb + OFF_B + (uint32_t)(buf ^ 1) * 34816u, ntj * 64, tid);
                if (tid < 4)
                    cp16(sb + OFF_CLS + (uint32_t)(buf ^ 1) * 64u + tid * 16u,
                         g_clsb + ntj * 64 + tid * 16);
                cp_commit();
                cp_wait1();
                pf = true;
            }
        }
        if (!pf) cp_wait0();
        __syncthreads();

        const uint32_t pBh = sb + OFF_B + (uint32_t)buf * 34816u + laneB;
        const uint32_t pBl = pBh + ATILE;

        float acc[2][2][4];
#pragma unroll
        for (int mf = 0; mf < 2; ++mf)
#pragma unroll
            for (int nf = 0; nf < 2; ++nf)
#pragma unroll
                for (int c4 = 0; c4 < 4; ++c4) acc[mf][nf][c4] = 0.f;

#pragma unroll 1
        for (int ks = 0; ks < 8; ++ks) {
            const uint32_t ko = (uint32_t)ks * 32u;
            uint32_t aH[2][4], aL[2][4], bh[4], bl[4];
            ldsm4(aH[0], pAh + ko);
            ldsm4(aH[1], pAh + 16u * RSB + ko);
            ldsm4(aL[0], pAl + ko);
            ldsm4(aL[1], pAl + 16u * RSB + ko);
            ldsm4(bh, pBh + ko);
            ldsm4(bl, pBl + ko);
#pragma unroll
            for (int nf = 0; nf < 2; ++nf)
#pragma unroll
                for (int mf = 0; mf < 2; ++mf)
                    mma_bf16(acc[mf][nf], aH[mf], bh[nf], bh[nf + 2]);
#pragma unroll
            for (int nf = 0; nf < 2; ++nf)
#pragma unroll
                for (int mf = 0; mf < 2; ++mf)
                    mma_bf16(acc[mf][nf], aH[mf], bl[nf], bl[nf + 2]);
#pragma unroll
            for (int nf = 0; nf < 2; ++nf)
#pragma unroll
                for (int mf = 0; mf < 2; ++mf)
                    mma_bf16(acc[mf][nf], aL[mf], bh[nf], bh[nf + 2]);
        }

        const uint32_t clsb_s = sb + OFF_CLS + (uint32_t)buf * 64u +
                                (uint32_t)(warp_n * 16 + 2 * (l & 3));
#pragma unroll
        for (int nf = 0; nf < 2; ++nf) {
            unsigned short cw;
            asm volatile("ld.shared.u16 %0, [%1];" : "=h"(cw) : "r"(clsb_s + (uint32_t)nf * 8u));
            const int cj0 = cw & 0xff, cj1 = cw >> 8;
            float cE0 = 0.f, cE1 = 0.f, cN0 = 0.f, cN1 = 0.f, cL0 = 0.f, cL1 = 0.f;
#pragma unroll
            for (int ri = 0; ri < 4; ++ri) {
                float v0 = acc[ri >> 1][nf][(ri & 1) * 2 + 0];
                float v1 = acc[ri >> 1][nf][(ri & 1) * 2 + 1];
                float e0 = ex2f(v0), e1 = ex2f(v1);
                if (cj0 == pc[ri]) { epos[ri] += e0; lsum[ri] += v0; cE0 += e0; cL0 += v0; }
                else if (cj0 == ncl[ri]) { eneg[ri] += e0; cN0 += e0; }
                if (cj1 == pc[ri]) { epos[ri] += e1; lsum[ri] += v1; cE1 += e1; cL1 += v1; }
                else if (cj1 == ncl[ri]) { eneg[ri] += e1; cN1 += e1; }
            }
            if (d != 0) {
#pragma unroll
                for (int s = 4; s <= 16; s <<= 1) {
                    cE0 += __shfl_xor_sync(0xffffffffu, cE0, s);
                    cE1 += __shfl_xor_sync(0xffffffffu, cE1, s);
                    cN0 += __shfl_xor_sync(0xffffffffu, cN0, s);
                    cN1 += __shfl_xor_sync(0xffffffffu, cN1, s);
                    cL0 += __shfl_xor_sync(0xffffffffu, cL0, s);
                    cL1 += __shfl_xor_sync(0xffffffffu, cL1, s);
                }
                if ((l >> 2) == 0) {
                    int col = warp_n * 16 + nf * 8 + 2 * l;
                    int base = (warp_m * 64 + col) * 3;
                    red[base + 0] = cE0; red[base + 1] = cN0; red[base + 2] = cL0;
                    red[base + 3] = cE1; red[base + 4] = cN1; red[base + 5] = cL1;
                }
            }
        }
        __syncthreads();
        if (d != 0 && tid < 64) {
            float E = red[tid * 3 + 0] + red[(64 + tid) * 3 + 0];
            float N = red[tid * 3 + 1] + red[(64 + tid) * 3 + 1];
            float L = red[tid * 3 + 2] + red[(64 + tid) * 3 + 2];
            g_cpart[d - 1][tj * 64 + tid] = make_float4(E, N, L, 0.f);
        }
        __syncthreads();
        if (pf) buf ^= 1;
    }

    if (curx >= 0) flush_rows(curx);
}

// ---------------------------------------------------------------- rowval + ticketed sum
__global__ void rowval_sum_kernel(float* __restrict__ out) {
    __shared__ bool is_last;
    __shared__ float s[256];
    int tid = threadIdx.x;
    int i = blockIdx.x * 64 + (tid >> 2);
    int p = tid & 3;
    float Ep = 0.f, En = 0.f, Ls = 0.f;
#pragma unroll
    for (int sl0 = 0; sl0 < 18; ++sl0) {
        int sl = p * 18 + sl0;               // 0..71
        float4 v = (sl < 8) ? g_rpart[sl][i] : g_cpart[sl - 8][i];
        Ep += v.x; En += v.y; Ls += v.z;
    }
#pragma unroll
    for (int o = 1; o <= 2; o <<= 1) {
        Ep += __shfl_xor_sync(0xffffffffu, Ep, o);
        En += __shfl_xor_sync(0xffffffffu, En, o);
        Ls += __shfl_xor_sync(0xffffffffu, Ls, o);
    }
    if (p == 0) {
        int ci = g_cls[i];
        int pcnt = g_cnt4[ci ^ 1];
        int ncnt = g_cnt4[ci ^ 2];
        float val = 0.f;
        if (pcnt > 0 && ncnt > 0)
            val = (Ls * 0.6931471805599453f - (float)pcnt * logf(Ep + En)) / (float)pcnt;
        g_rowval[i] = val;
    }
    // last-block sum (deterministic: single block, fixed order)
    __threadfence();
    __syncthreads();
    if (tid == 0) is_last = (atomicAdd(&g_ticket, 1) == gridDim.x - 1);
    __syncthreads();
    if (is_last) {
        float acc = 0.f;
        for (int k = tid; k < B_SZ; k += 256) acc += g_rowval[k];
        s[tid] = acc;
        __syncthreads();
        for (int o = 128; o; o >>= 1) {
            if (tid < o) s[tid] += s[tid + o];
            __syncthreads();
        }
        if (tid == 0) out[0] = -s[0] / (float)B_SZ;
    }
}

// ---------------------------------------------------------------- launch
extern "C" void kernel_launch(void* const* d_in, const int* in_sizes, int n_in,
                              void* d_out, int out_size) {
    const float* F = (const float*)d_in[0];
    const void* dix = d_in[1];
    const void* tt  = d_in[2];
    const void* tp  = d_in[3];
    float* out = (float*)d_out;

    cls_zero_kernel<<<288, 256>>>(dix, tt, tp);
    scatter_kernel<<<32, 256>>>();
    prep_joblist_kernel<<<1025, 256>>>(F);

    cudaFuncSetAttribute(main_kernel, cudaFuncAttributeMaxDynamicSharedMemorySize, SMEM_BYTES);
    main_kernel<<<NCTA, 256, SMEM_BYTES>>>();

    rowval_sum_kernel<<<128, 256>>>(out);
}

// round 16
// speedup vs baseline: 2.1271x; 1.1007x over previous
#include <cuda_runtime.h>
#include <cuda_bf16.h>
#include <cstdint>

// ContrastiveLoss B=8192 D=128 T=0.1, classes c=2*tt+tp in {0..3}
// Round 16: R15 + (1) mode-specialized epilogue (pure-pos / pure-neg tiles are
// compare-free; mode encoded in job word), (2) atomicAdd accumulators replace
// the 72-slice partial buffers (kills 4.6MB zeroing + 9.4MB rowval gather).

#define B_SZ 8192
#define RSB  272u
#define ATILE 17408u              // 64 rows * 272
#define OFF_B   34816u            // + buf*34816 ; hi +0, lo +17408
#define OFF_CLS 104448u           // + buf*64
#define OFF_RED 104576u           // 3072 B scratch
#define SMEM_BYTES (104576 + 3072 + 1024)
#define NCTA 296

// ---------------------------------------------------------------- globals
__device__ __align__(256) __nv_bfloat16 g_hi[B_SZ * 128];
__device__ __align__(256) __nv_bfloat16 g_lo[B_SZ * 128];
__device__ int           g_cls_orig[B_SZ];
__device__ int           g_newpos[B_SZ];
__device__ int           g_cls[B_SZ];
__device__ __align__(256) unsigned char g_clsb[B_SZ];
__device__ int           g_blkcnt[32][4];
__device__ int           g_cnt4[4];
__device__ int           g_joblist[8448];    // (mode<<16)|(x<<8)|d, grouped by x
__device__ int           g_njobs;
__device__ float         g_Ep[B_SZ];         // atomic accumulators
__device__ float         g_En[B_SZ];
__device__ float         g_Ls[B_SZ];
__device__ float         g_rowval[B_SZ];
__device__ int           g_ticket;

// ---------------------------------------------------------------- helpers
__device__ __forceinline__ uint32_t smem_u32(const void* p) {
    uint32_t a;
    asm("{ .reg .u64 t; cvta.to.shared.u64 t, %1; cvt.u32.u64 %0, t; }" : "=r"(a) : "l"(p));
    return a;
}
__device__ __forceinline__ void cp16(uint32_t dst, const void* src) {
    asm volatile("cp.async.cg.shared.global [%0], [%1], 16;" :: "r"(dst), "l"(src) : "memory");
}
__device__ __forceinline__ void cp_commit() {
    asm volatile("cp.async.commit_group;" ::: "memory");
}
__device__ __forceinline__ void cp_wait0() {
    asm volatile("cp.async.wait_group 0;" ::: "memory");
}
__device__ __forceinline__ void cp_wait1() {
    asm volatile("cp.async.wait_group 1;" ::: "memory");
}
__device__ __forceinline__ void ldsm4(uint32_t* r, uint32_t addr) {
    asm volatile("ldmatrix.sync.aligned.m8n8.x4.shared.b16 {%0,%1,%2,%3}, [%4];"
                 : "=r"(r[0]), "=r"(r[1]), "=r"(r[2]), "=r"(r[3]) : "r"(addr));
}
__device__ __forceinline__ void mma_bf16(float* c, const uint32_t* a, uint32_t b0, uint32_t b1) {
    asm volatile(
        "mma.sync.aligned.m16n8k16.row.col.f32.bf16.bf16.f32 "
        "{%0,%1,%2,%3}, {%4,%5,%6,%7}, {%8,%9}, {%0,%1,%2,%3};"
        : "+f"(c[0]), "+f"(c[1]), "+f"(c[2]), "+f"(c[3])
        : "r"(a[0]), "r"(a[1]), "r"(a[2]), "r"(a[3]), "r"(b0), "r"(b1));
}
__device__ __forceinline__ float ex2f(float v) {
    float e;
    asm("ex2.approx.ftz.f32 %0, %1;" : "=f"(e) : "f"(v));
    return e;
}

__device__ __forceinline__ void load_tile64(uint32_t sdst_h, int rowbase, int tid) {
#pragma unroll
    for (int i = 0; i < 4; ++i) {
        int idx = tid + i * 256;
        int r = idx >> 4, c = idx & 15;
        uint32_t dst = sdst_h + (uint32_t)r * RSB + (uint32_t)c * 16u;
        cp16(dst, g_hi + (size_t)(rowbase + r) * 128 + c * 8);
        cp16(dst + ATILE, g_lo + (size_t)(rowbase + r) * 128 + c * 8);
    }
}

// ---------------------------------------------------------------- cls + counts + zero (+detect)
// grid 288: blocks 0..31: classes + counts (+local detect); blocks 32..63:
// zero Ep/En/Ls (256 rows each); block 32 zeroes ticket. Blocks 64+ idle-exit.
__global__ void cls_zero_kernel(const void* __restrict__ data_ix,
                                const void* __restrict__ tt,
                                const void* __restrict__ tp) {
    int b = blockIdx.x, tid = threadIdx.x;
    if (b < 32) {
        __shared__ int hc[4];
        __shared__ int bad;
        if (tid < 4) hc[tid] = 0;
        if (tid == 0) bad = 0;
        __syncthreads();
        {
            long long v = ((const long long*)data_ix)[(b & 15) * 256 + tid];
            if (v < 0 || v >= 100000) atomicOr(&bad, 1);
        }
        __syncthreads();
        const bool is64 = (bad == 0);
        int i = b * 256 + tid;
        int t, p;
        if (is64) {
            long long ix = ((const long long*)data_ix)[i];
            t = (int)((const long long*)tt)[ix];
            p = (int)((const long long*)tp)[ix];
        } else {
            int ix = ((const int*)data_ix)[i];
            t = ((const int*)tt)[ix];
            p = ((const int*)tp)[ix];
        }
        int c = t * 2 + p;
        g_cls_orig[i] = c;
        atomicAdd(&hc[c], 1);
        __syncthreads();
        if (tid < 4) g_blkcnt[b][tid] = hc[tid];
    } else if (b < 64) {
        int i = (b - 32) * 256 + tid;
        g_Ep[i] = 0.f; g_En[i] = 0.f; g_Ls[i] = 0.f;
        if (b == 32 && tid == 0) g_ticket = 0;
    }
}

// ---------------------------------------------------------------- scatter (+inlined scan)
__global__ void scatter_kernel() {
    __shared__ int blkoff[32][4];
    __shared__ int wcnt[8][4];
    __shared__ int wbase[8][4];
    int b = blockIdx.x, tid = threadIdx.x, lane = tid & 31, w = tid >> 5;

    if (tid < 128) {
        int w2 = tid >> 5;
        int v = g_blkcnt[lane][w2];
        int own = v;
#pragma unroll
        for (int o = 1; o < 32; o <<= 1) {
            int u = __shfl_up_sync(0xffffffffu, v, o);
            if (lane >= o) v += u;
        }
        int total = __shfl_sync(0xffffffffu, v, 31);
        wcnt[0][w2] = total;
        __syncthreads();
        int base = 0;
        for (int c = 0; c < 4; ++c) base += (c < w2) ? wcnt[0][c] : 0;
        blkoff[lane][w2] = base + (v - own);
        if (lane == 0 && b == 0) g_cnt4[w2] = total;
    } else {
        __syncthreads();
    }
    __syncthreads();

    int i = b * 256 + tid;
    int c = g_cls_orig[i];
    unsigned b0 = __ballot_sync(0xffffffffu, c == 0);
    unsigned b1 = __ballot_sync(0xffffffffu, c == 1);
    unsigned b2 = __ballot_sync(0xffffffffu, c == 2);
    unsigned b3 = __ballot_sync(0xffffffffu, c == 3);
    unsigned mb = (c == 0) ? b0 : (c == 1) ? b1 : (c == 2) ? b2 : b3;
    int lanerank = __popc(mb & ((1u << lane) - 1u));
    if (lane == 0) {
        wcnt[w][0] = __popc(b0); wcnt[w][1] = __popc(b1);
        wcnt[w][2] = __popc(b2); wcnt[w][3] = __popc(b3);
    }
    __syncthreads();
    if (tid < 32) {
        int cc = tid >> 3, ww = tid & 7;
        int s = 0;
        for (int u = 0; u < ww; ++u) s += wcnt[u][cc];
        wbase[ww][cc] = s;
    }
    __syncthreads();
    int np = blkoff[b][c] + wbase[w][c] + lanerank;
    g_newpos[i] = np;
    g_cls[np] = c;
    g_clsb[np] = (unsigned char)c;
}

// ---------------------------------------------------------------- prep (+joblist in block 1024)
__global__ void prep_joblist_kernel(const float* __restrict__ F) {
    if (blockIdx.x == 1024) {
        __shared__ int woff[4];
        __shared__ unsigned char bc[128];
        int x = threadIdx.x;
        if (x >= 128) return;
        int lane = x & 31, w = x >> 5;
        {
            int c0 = g_cls[x * 64], c1 = g_cls[x * 64 + 63];
            bc[x] = (c0 == c1) ? (unsigned char)c0 : (unsigned char)255;
        }
        __syncwarp();
        asm volatile("bar.sync 1, 128;" ::: "memory");
        int bcx = bc[x];
        int n = 0;
#pragma unroll 1
        for (int d = 0; d <= 64; ++d) {
            if (d == 64 && x >= 64) break;
            int tj = (x + d) & 127;
            int bcj = bc[tj];
            int xr = bcx ^ bcj;
            bool skip = (bcx < 4 && bcj < 4) && (xr != 1) && (xr != 2);
            if (!skip) ++n;
        }
        int v = n;
#pragma unroll
        for (int o = 1; o < 32; o <<= 1) {
            int u = __shfl_up_sync(0xffffffffu, v, o);
            if (lane >= o) v += u;
        }
        if (lane == 31) woff[w] = v;
        int ex = v - n;
        asm volatile("bar.sync 1, 128;" ::: "memory");
        if (x == 0) {
            int run = 0;
            for (int u = 0; u < 4; ++u) { int tmp = woff[u]; woff[u] = run; run += tmp; }
            g_njobs = run;
        }
        asm volatile("bar.sync 1, 128;" ::: "memory");
        int pos = woff[w] + ex;
#pragma unroll 1
        for (int d = 0; d <= 64; ++d) {
            if (d == 64 && x >= 64) break;
            int tj = (x + d) & 127;
            int bcj = bc[tj];
            int xr = bcx ^ bcj;
            bool pure = (bcx < 4 && bcj < 4);
            bool skip = pure && (xr != 1) && (xr != 2);
            if (!skip) {
                int mode = pure ? ((xr == 1) ? 1 : 2) : 0;
                g_joblist[pos++] = (mode << 16) | (x << 8) | d;
            }
        }
        return;
    }
    int warp = (blockIdx.x * blockDim.x + threadIdx.x) >> 5;
    int lane = threadIdx.x & 31;
    const float* row = F + (size_t)warp * 128;
    float v0 = row[lane], v1 = row[lane + 32], v2 = row[lane + 64], v3 = row[lane + 96];
    float ss = v0 * v0 + v1 * v1 + v2 * v2 + v3 * v3;
#pragma unroll
    for (int o = 16; o; o >>= 1) ss += __shfl_xor_sync(0xffffffffu, ss, o);
    float scale = sqrtf(14.4269504088896f) / sqrtf(ss);
    int np = g_newpos[warp];
    float g[4] = {v0 * scale, v1 * scale, v2 * scale, v3 * scale};
#pragma unroll
    for (int qq = 0; qq < 4; ++qq) {
        __nv_bfloat16 h = __float2bfloat16(g[qq]);
        __nv_bfloat16 lo = __float2bfloat16(g[qq] - __bfloat162float(h));
        g_hi[(size_t)np * 128 + lane + qq * 32] = h;
        g_lo[(size_t)np * 128 + lane + qq * 32] = lo;
    }
}

// ---------------------------------------------------------------- main kernel
__global__ void __launch_bounds__(256, 2) main_kernel() {
    extern __shared__ char smraw[];
    char* smp = (char*)(((uintptr_t)smraw + 1023) & ~(uintptr_t)1023);
    const uint32_t sb = smem_u32(smp);
    float* red = (float*)(smp + OFF_RED);

    const int tid = threadIdx.x;
    const int l = tid & 31, wid = tid >> 5;
    const int warp_m = wid >> 2, warp_n = wid & 3;
    const int cta = blockIdx.x;

    const int M = g_njobs;
    const int jstart = (int)(((long long)cta * M) / NCTA);
    const int jend   = (int)(((long long)(cta + 1) * M) / NCTA);

    const uint32_t laneA = (uint32_t)((warp_m * 32 + (l & 15)) * (int)RSB + ((l >> 4) * 16));
    const uint32_t pAh = sb + laneA;
    const uint32_t pAl = sb + ATILE + laneA;
    const uint32_t laneB = (uint32_t)((warp_n * 16 + (l & 15)) * (int)RSB + ((l >> 4) * 16));

    float epos[4] = {0.f, 0.f, 0.f, 0.f};
    float eneg[4] = {0.f, 0.f, 0.f, 0.f};
    float lsum[4] = {0.f, 0.f, 0.f, 0.f};
    int pc[4], ncl[4];
    int curx = -1, buf = 0;

    auto flush_rows = [&](int fx) {
#pragma unroll
        for (int ri = 0; ri < 4; ++ri) {
            epos[ri] += __shfl_xor_sync(0xffffffffu, epos[ri], 1);
            epos[ri] += __shfl_xor_sync(0xffffffffu, epos[ri], 2);
            eneg[ri] += __shfl_xor_sync(0xffffffffu, eneg[ri], 1);
            eneg[ri] += __shfl_xor_sync(0xffffffffu, eneg[ri], 2);
            lsum[ri] += __shfl_xor_sync(0xffffffffu, lsum[ri], 1);
            lsum[ri] += __shfl_xor_sync(0xffffffffu, lsum[ri], 2);
        }
        if ((l & 3) == 0) {
#pragma unroll
            for (int ri = 0; ri < 4; ++ri) {
                int row = warp_m * 32 + (ri >> 1) * 16 + (ri & 1) * 8 + (l >> 2);
                int gi = fx * 64 + row;
                atomicAdd(&g_Ep[gi], epos[ri]);
                atomicAdd(&g_En[gi], eneg[ri]);
                atomicAdd(&g_Ls[gi], lsum[ri]);
            }
        }
#pragma unroll
        for (int ri = 0; ri < 4; ++ri) { epos[ri] = 0.f; eneg[ri] = 0.f; lsum[ri] = 0.f; }
    };

    for (int j = jstart; j < jend; ++j) {
        const int job = g_joblist[j];
        const int x = (job >> 8) & 255, d = job & 255, mode = job >> 16;
        const int tj = (x + d) & 127;

        if (x != curx) {
            if (curx >= 0) flush_rows(curx);
            load_tile64(sb + 0u, x * 64, tid);
            load_tile64(sb + OFF_B, tj * 64, tid);
            if (tid < 4) cp16(sb + OFF_CLS + tid * 16u, g_clsb + tj * 64 + tid * 16);
            cp_commit();
            cp_wait0();
            __syncthreads();
            buf = 0;
            curx = x;
#pragma unroll
            for (int ri = 0; ri < 4; ++ri) {
                int row = warp_m * 32 + (ri >> 1) * 16 + (ri & 1) * 8 + (l >> 2);
                int cr = g_cls[x * 64 + row];
                pc[ri] = cr ^ 1;
                ncl[ri] = cr ^ 2;
            }
        }

        bool pf = false;
        if (j + 1 < jend) {
            int nj = g_joblist[j + 1];
            if (((nj >> 8) & 255) == x) {
                int ntj = (x + (nj & 255)) & 127;
                load_tile64(sb + OFF_B + (uint32_t)(buf ^ 1) * 34816u, ntj * 64, tid);
                if (tid < 4)
                    cp16(sb + OFF_CLS + (uint32_t)(buf ^ 1) * 64u + tid * 16u,
                         g_clsb + ntj * 64 + tid * 16);
                cp_commit();
                cp_wait1();
                pf = true;
            }
        }
        if (!pf) cp_wait0();
        __syncthreads();

        // ---------------- MMA: 64x64 tile, K=128, 3 splits
        const uint32_t pBh = sb + OFF_B + (uint32_t)buf * 34816u + laneB;
        const uint32_t pBl = pBh + ATILE;

        float acc[2][2][4];
#pragma unroll
        for (int mf = 0; mf < 2; ++mf)
#pragma unroll
            for (int nf = 0; nf < 2; ++nf)
#pragma unroll
                for (int c4 = 0; c4 < 4; ++c4) acc[mf][nf][c4] = 0.f;

#pragma unroll 1
        for (int ks = 0; ks < 8; ++ks) {
            const uint32_t ko = (uint32_t)ks * 32u;
            uint32_t aH[2][4], aL[2][4], bh[4], bl[4];
            ldsm4(aH[0], pAh + ko);
            ldsm4(aH[1], pAh + 16u * RSB + ko);
            ldsm4(aL[0], pAl + ko);
            ldsm4(aL[1], pAl + 16u * RSB + ko);
            ldsm4(bh, pBh + ko);
            ldsm4(bl, pBl + ko);
#pragma unroll
            for (int nf = 0; nf < 2; ++nf)
#pragma unroll
                for (int mf = 0; mf < 2; ++mf)
                    mma_bf16(acc[mf][nf], aH[mf], bh[nf], bh[nf + 2]);
#pragma unroll
            for (int nf = 0; nf < 2; ++nf)
#pragma unroll
                for (int mf = 0; mf < 2; ++mf)
                    mma_bf16(acc[mf][nf], aH[mf], bl[nf], bl[nf + 2]);
#pragma unroll
            for (int nf = 0; nf < 2; ++nf)
#pragma unroll
                for (int mf = 0; mf < 2; ++mf)
                    mma_bf16(acc[mf][nf], aL[mf], bh[nf], bh[nf + 2]);
        }

        // ---------------- epilogue, mode-specialized (mode is CTA-uniform)
        if (mode == 0) {
            const uint32_t clsb_s = sb + OFF_CLS + (uint32_t)buf * 64u +
                                    (uint32_t)(warp_n * 16 + 2 * (l & 3));
#pragma unroll
            for (int nf = 0; nf < 2; ++nf) {
                unsigned short cw;
                asm volatile("ld.shared.u16 %0, [%1];" : "=h"(cw) : "r"(clsb_s + (uint32_t)nf * 8u));
                const int cj0 = cw & 0xff, cj1 = cw >> 8;
                float cE0 = 0.f, cE1 = 0.f, cN0 = 0.f, cN1 = 0.f, cL0 = 0.f, cL1 = 0.f;
#pragma unroll
                for (int ri = 0; ri < 4; ++ri) {
                    float v0 = acc[ri >> 1][nf][(ri & 1) * 2 + 0];
                    float v1 = acc[ri >> 1][nf][(ri & 1) * 2 + 1];
                    float e0 = ex2f(v0), e1 = ex2f(v1);
                    if (cj0 == pc[ri]) { epos[ri] += e0; lsum[ri] += v0; cE0 += e0; cL0 += v0; }
                    else if (cj0 == ncl[ri]) { eneg[ri] += e0; cN0 += e0; }
                    if (cj1 == pc[ri]) { epos[ri] += e1; lsum[ri] += v1; cE1 += e1; cL1 += v1; }
                    else if (cj1 == ncl[ri]) { eneg[ri] += e1; cN1 += e1; }
                }
                if (d != 0) {
#pragma unroll
                    for (int s = 4; s <= 16; s <<= 1) {
                        cE0 += __shfl_xor_sync(0xffffffffu, cE0, s);
                        cE1 += __shfl_xor_sync(0xffffffffu, cE1, s);
                        cN0 += __shfl_xor_sync(0xffffffffu, cN0, s);
                        cN1 += __shfl_xor_sync(0xffffffffu, cN1, s);
                        cL0 += __shfl_xor_sync(0xffffffffu, cL0, s);
                        cL1 += __shfl_xor_sync(0xffffffffu, cL1, s);
                    }
                    if ((l >> 2) == 0) {
                        int col = warp_n * 16 + nf * 8 + 2 * l;
                        int base = (warp_m * 64 + col) * 3;
                        red[base + 0] = cE0; red[base + 1] = cN0; red[base + 2] = cL0;
                        red[base + 3] = cE1; red[base + 4] = cN1; red[base + 5] = cL1;
                    }
                }
            }
        } else if (mode == 1) {
            // pure positive tile: every element feeds epos/lsum (no compares)
#pragma unroll
            for (int nf = 0; nf < 2; ++nf) {
                float cE0 = 0.f, cE1 = 0.f, cL0 = 0.f, cL1 = 0.f;
#pragma unroll
                for (int ri = 0; ri < 4; ++ri) {
                    float v0 = acc[ri >> 1][nf][(ri & 1) * 2 + 0];
                    float v1 = acc[ri >> 1][nf][(ri & 1) * 2 + 1];
                    float e0 = ex2f(v0), e1 = ex2f(v1);
                    epos[ri] += e0 + e1;
                    lsum[ri] += v0 + v1;
                    cE0 += e0; cE1 += e1; cL0 += v0; cL1 += v1;
                }
#pragma unroll
                for (int s = 4; s <= 16; s <<= 1) {
                    cE0 += __shfl_xor_sync(0xffffffffu, cE0, s);
                    cE1 += __shfl_xor_sync(0xffffffffu, cE1, s);
                    cL0 += __shfl_xor_sync(0xffffffffu, cL0, s);
                    cL1 += __shfl_xor_sync(0xffffffffu, cL1, s);
                }
                if ((l >> 2) == 0) {
                    int col = warp_n * 16 + nf * 8 + 2 * l;
                    int base = (warp_m * 64 + col) * 3;
                    red[base + 0] = cE0; red[base + 1] = 0.f; red[base + 2] = cL0;
                    red[base + 3] = cE1; red[base + 4] = 0.f; red[base + 5] = cL1;
                }
            }
        } else {
            // pure negative tile: every element feeds eneg only
#pragma unroll
            for (int nf = 0; nf < 2; ++nf) {
                float cN0 = 0.f, cN1 = 0.f;
#pragma unroll
                for (int ri = 0; ri < 4; ++ri) {
                    float v0 = acc[ri >> 1][nf][(ri & 1) * 2 + 0];
                    float v1 = acc[ri >> 1][nf][(ri & 1) * 2 + 1];
                    float e0 = ex2f(v0), e1 = ex2f(v1);
                    eneg[ri] += e0 + e1;
                    cN0 += e0; cN1 += e1;
                }
#pragma unroll
                for (int s = 4; s <= 16; s <<= 1) {
                    cN0 += __shfl_xor_sync(0xffffffffu, cN0, s);
                    cN1 += __shfl_xor_sync(0xffffffffu, cN1, s);
                }
                if ((l >> 2) == 0) {
                    int col = warp_n * 16 + nf * 8 + 2 * l;
                    int base = (warp_m * 64 + col) * 3;
                    red[base + 0] = 0.f; red[base + 1] = cN0; red[base + 2] = 0.f;
                    red[base + 3] = 0.f; red[base + 4] = cN1; red[base + 5] = 0.f;
                }
            }
        }
        __syncthreads();
        if (d != 0 && tid < 64) {
            float E = red[tid * 3 + 0] + red[(64 + tid) * 3 + 0];
            float N = red[tid * 3 + 1] + red[(64 + tid) * 3 + 1];
            float L = red[tid * 3 + 2] + red[(64 + tid) * 3 + 2];
            int gi = tj * 64 + tid;
            atomicAdd(&g_Ep[gi], E);
            atomicAdd(&g_En[gi], N);
            atomicAdd(&g_Ls[gi], L);
        }
        __syncthreads();
        if (pf) buf ^= 1;
    }

    if (curx >= 0) flush_rows(curx);
}

// ---------------------------------------------------------------- rowval + ticketed sum
__global__ void rowval_sum_kernel(float* __restrict__ out) {
    __shared__ bool is_last;
    __shared__ float s[256];
    int tid = threadIdx.x;
    int i = blockIdx.x * 256 + tid;
    {
        float Ep = g_Ep[i], En = g_En[i], Ls = g_Ls[i];
        int ci = g_cls[i];
        int pcnt = g_cnt4[ci ^ 1];
        int ncnt = g_cnt4[ci ^ 2];
        float val = 0.f;
        if (pcnt > 0 && ncnt > 0)
            val = (Ls * 0.6931471805599453f - (float)pcnt * logf(Ep + En)) / (float)pcnt;
        g_rowval[i] = val;
    }
    __threadfence();
    __syncthreads();
    if (tid == 0) is_last = (atomicAdd(&g_ticket, 1) == gridDim.x - 1);
    __syncthreads();
    if (is_last) {
        float acc = 0.f;
        for (int k = tid; k < B_SZ; k += 256) acc += g_rowval[k];
        s[tid] = acc;
        __syncthreads();
        for (int o = 128; o; o >>= 1) {
            if (tid < o) s[tid] += s[tid + o];
            __syncthreads();
        }
        if (tid == 0) out[0] = -s[0] / (float)B_SZ;
    }
}

// ---------------------------------------------------------------- launch
extern "C" void kernel_launch(void* const* d_in, const int* in_sizes, int n_in,
                              void* d_out, int out_size) {
    const float* F = (const float*)d_in[0];
    const void* dix = d_in[1];
    const void* tt  = d_in[2];
    const void* tp  = d_in[3];
    float* out = (float*)d_out;

    cls_zero_kernel<<<64, 256>>>(dix, tt, tp);
    scatter_kernel<<<32, 256>>>();
    prep_joblist_kernel<<<1025, 256>>>(F);

    cudaFuncSetAttribute(main_kernel, cudaFuncAttributeMaxDynamicSharedMemorySize, SMEM_BYTES);
    main_kernel<<<NCTA, 256, SMEM_BYTES>>>();

    rowval_sum_kernel<<<32, 256>>>(out);
}